// round 2
// baseline (speedup 1.0000x reference)
#include <cuda_runtime.h>

// Problem dims
#define BB   32
#define SS   512
#define DDIM 512
#define HH   8
#define DK   64
#define FFW  200
#define MROWS (BB * SS)          // 16384
#define LN_N  (SS * DDIM)        // 262144 elements per batch for 2-D LayerNorm

// ---------------- scratch (static device globals; no allocation) -------------
__device__ float g_q[MROWS * DDIM];
__device__ float g_k[MROWS * DDIM];
__device__ float g_v[MROWS * DDIM];
__device__ float g_scores[(long)BB * HH * SS * SS];   // 268 MB
__device__ float g_concat[MROWS * DDIM];
__device__ float g_y[MROWS * DDIM];
__device__ float g_f1[MROWS * FFW];
__device__ float g_f2[MROWS * FFW];
__device__ float g_f3[MROWS * DDIM];
__device__ float g_y2[MROWS * DDIM];

// ---------------- generic tiled SGEMM ----------------------------------------
// C[m,n] = alpha * sum_k A[m,k] * B(n,k or k,n)  (+bias[n]) (+Res[m,n]) (relu?)
// Batch offset: z = blockIdx.z ; off = (z/zdiv)*s?  + (z%zdiv)*s?2
// Assumes: M % BM == 0, K % BK == 0, K % 4 == 0. N handled with guards.
template<int BM, int BN, int BK, int TM, int TN, bool TB, bool RELU>
__global__ __launch_bounds__((BM/TM)*(BN/TN))
void gemm_kernel(const float* __restrict__ A, const float* __restrict__ Bm,
                 const float* __restrict__ bias, const float* __restrict__ Res,
                 float* __restrict__ C,
                 int M, int N, int K, int lda, int ldb, int ldc,
                 long sA, long sA2, long sB, long sB2, long sC, long sC2,
                 int zdiv, float alpha)
{
    constexpr int NT = (BM/TM)*(BN/TN);
    __shared__ float As[BK][BM];
    __shared__ float Bs[BK][BN];

    const int bz = blockIdx.z;
    const long zo1 = bz / zdiv, zo2 = bz % zdiv;
    A  += zo1 * sA + zo2 * sA2;
    Bm += zo1 * sB + zo2 * sB2;
    C  += zo1 * sC + zo2 * sC2;
    if (Res) Res += zo1 * sC + zo2 * sC2;

    const int tid  = threadIdx.x;
    const int mBlk = blockIdx.y * BM;
    const int nBlk = blockIdx.x * BN;
    const int tr = tid / (BN/TN);
    const int tc = tid % (BN/TN);

    float acc[TM][TN] = {};

    for (int kt = 0; kt < K; kt += BK) {
        // ---- load A tile (row-major, K contiguous) ----
        for (int i = tid*4; i < BM*BK; i += NT*4) {
            int r = i / BK, kk = i % BK;
            float4 va = *reinterpret_cast<const float4*>(&A[(long)(mBlk + r)*lda + kt + kk]);
            As[kk+0][r] = va.x; As[kk+1][r] = va.y; As[kk+2][r] = va.z; As[kk+3][r] = va.w;
        }
        // ---- load B tile ----
        if (TB) {
            // B is [N,K], K contiguous
            for (int i = tid*4; i < BN*BK; i += NT*4) {
                int r = i / BK, kk = i % BK;
                int gn = nBlk + r;
                float4 vb;
                if (gn < N) vb = *reinterpret_cast<const float4*>(&Bm[(long)gn*ldb + kt + kk]);
                else        vb = make_float4(0.f, 0.f, 0.f, 0.f);
                Bs[kk+0][r] = vb.x; Bs[kk+1][r] = vb.y; Bs[kk+2][r] = vb.z; Bs[kk+3][r] = vb.w;
            }
        } else {
            // B is [K,N], N contiguous
            for (int i = tid*4; i < BK*BN; i += NT*4) {
                int kk = i / BN, n = i % BN;
                int gn = nBlk + n;
                float4 vb;
                if (gn + 3 < N) {
                    vb = *reinterpret_cast<const float4*>(&Bm[(long)(kt+kk)*ldb + gn]);
                } else {
                    vb.x = (gn+0 < N) ? Bm[(long)(kt+kk)*ldb + gn+0] : 0.f;
                    vb.y = (gn+1 < N) ? Bm[(long)(kt+kk)*ldb + gn+1] : 0.f;
                    vb.z = (gn+2 < N) ? Bm[(long)(kt+kk)*ldb + gn+2] : 0.f;
                    vb.w = (gn+3 < N) ? Bm[(long)(kt+kk)*ldb + gn+3] : 0.f;
                }
                *reinterpret_cast<float4*>(&Bs[kk][n]) = vb;
            }
        }
        __syncthreads();

        #pragma unroll
        for (int kk = 0; kk < BK; kk++) {
            float rm[TM], rn[TN];
            #pragma unroll
            for (int i = 0; i < TM; i++) rm[i] = As[kk][tr*TM + i];
            #pragma unroll
            for (int j = 0; j < TN; j++) rn[j] = Bs[kk][tc*TN + j];
            #pragma unroll
            for (int i = 0; i < TM; i++)
                #pragma unroll
                for (int j = 0; j < TN; j++)
                    acc[i][j] += rm[i] * rn[j];
        }
        __syncthreads();
    }

    // ---- epilogue ----
    const int rowBase = mBlk + tr*TM;
    const int colBase = nBlk + tc*TN;
    #pragma unroll
    for (int i = 0; i < TM; i++) {
        #pragma unroll
        for (int j = 0; j < TN; j++) {
            int gc = colBase + j;
            if (gc < N) {
                float val = acc[i][j] * alpha;
                if (bias) val += bias[gc];
                if (Res)  val += Res[(long)(rowBase+i)*ldc + gc];
                if (RELU) val = fmaxf(val, 0.f);
                C[(long)(rowBase+i)*ldc + gc] = val;
            }
        }
    }
}

// ---------------- row softmax over width 512 ----------------------------------
__global__ __launch_bounds__(128)
void softmax_kernel(float* __restrict__ sc)
{
    __shared__ float red[4];
    const long row = blockIdx.x;
    float4* p = reinterpret_cast<float4*>(sc) + row * 128 + threadIdx.x;
    float4 v = *p;
    const int lane = threadIdx.x & 31, wid = threadIdx.x >> 5;

    float m = fmaxf(fmaxf(v.x, v.y), fmaxf(v.z, v.w));
    #pragma unroll
    for (int o = 16; o; o >>= 1) m = fmaxf(m, __shfl_xor_sync(0xffffffffu, m, o));
    if (!lane) red[wid] = m;
    __syncthreads();
    m = fmaxf(fmaxf(red[0], red[1]), fmaxf(red[2], red[3]));
    __syncthreads();   // protect red reuse

    v.x = __expf(v.x - m); v.y = __expf(v.y - m);
    v.z = __expf(v.z - m); v.w = __expf(v.w - m);
    float s = (v.x + v.y) + (v.z + v.w);
    #pragma unroll
    for (int o = 16; o; o >>= 1) s += __shfl_xor_sync(0xffffffffu, s, o);
    if (!lane) red[wid] = s;
    __syncthreads();
    s = (red[0] + red[1]) + (red[2] + red[3]);

    const float inv = 1.f / s;
    v.x *= inv; v.y *= inv; v.z *= inv; v.w *= inv;
    *p = v;
}

// ---------------- 2-D LayerNorm over (S,D) per batch ---------------------------
// out = ((X[+Add]) - mean) * rstd * gamma + beta ; mean/var over all 262144 elems
__global__ __launch_bounds__(1024)
void layernorm_kernel(const float* __restrict__ X, const float* __restrict__ Add,
                      const float* __restrict__ gamma, const float* __restrict__ beta,
                      float* __restrict__ out)
{
    const long base = (long)blockIdx.x * LN_N;
    float s1 = 0.f, s2 = 0.f;
    for (int i = threadIdx.x*4; i < LN_N; i += 4096) {
        float4 v = *reinterpret_cast<const float4*>(X + base + i);
        if (Add) {
            float4 a = *reinterpret_cast<const float4*>(Add + base + i);
            v.x += a.x; v.y += a.y; v.z += a.z; v.w += a.w;
        }
        s1 += (v.x + v.y) + (v.z + v.w);
        s2 += (v.x*v.x + v.y*v.y) + (v.z*v.z + v.w*v.w);
    }
    __shared__ float r1[32], r2[32];
    const int lane = threadIdx.x & 31, wid = threadIdx.x >> 5;
    #pragma unroll
    for (int o = 16; o; o >>= 1) {
        s1 += __shfl_xor_sync(0xffffffffu, s1, o);
        s2 += __shfl_xor_sync(0xffffffffu, s2, o);
    }
    if (!lane) { r1[wid] = s1; r2[wid] = s2; }
    __syncthreads();
    if (threadIdx.x < 32) {
        s1 = r1[threadIdx.x]; s2 = r2[threadIdx.x];
        #pragma unroll
        for (int o = 16; o; o >>= 1) {
            s1 += __shfl_xor_sync(0xffffffffu, s1, o);
            s2 += __shfl_xor_sync(0xffffffffu, s2, o);
        }
        if (!threadIdx.x) { r1[0] = s1; r2[0] = s2; }
    }
    __syncthreads();
    const float mean = r1[0] / (float)LN_N;
    const float var  = r2[0] / (float)LN_N - mean * mean;
    const float rstd = rsqrtf(var + 1e-5f);

    for (int i = threadIdx.x*4; i < LN_N; i += 4096) {
        float4 v = *reinterpret_cast<const float4*>(X + base + i);
        if (Add) {
            float4 a = *reinterpret_cast<const float4*>(Add + base + i);
            v.x += a.x; v.y += a.y; v.z += a.z; v.w += a.w;
        }
        float4 g  = *reinterpret_cast<const float4*>(gamma + i);
        float4 bt = *reinterpret_cast<const float4*>(beta  + i);
        float4 o;
        o.x = (v.x - mean) * rstd * g.x + bt.x;
        o.y = (v.y - mean) * rstd * g.y + bt.y;
        o.z = (v.z - mean) * rstd * g.z + bt.z;
        o.w = (v.w - mean) * rstd * g.w + bt.w;
        *reinterpret_cast<float4*>(out + base + i) = o;
    }
}

// ---------------- launch --------------------------------------------------------
extern "C" void kernel_launch(void* const* d_in, const int* in_sizes, int n_in,
                              void* d_out, int out_size)
{
    const float* x  = (const float*)d_in[0];
    const float* Wq = (const float*)d_in[1];
    const float* bq = (const float*)d_in[2];
    const float* Wk = (const float*)d_in[3];
    const float* bk = (const float*)d_in[4];
    const float* Wv = (const float*)d_in[5];
    const float* bv = (const float*)d_in[6];
    const float* Wo = (const float*)d_in[7];
    const float* bo = (const float*)d_in[8];
    const float* W1 = (const float*)d_in[9];
    const float* b1 = (const float*)d_in[10];
    const float* W2 = (const float*)d_in[11];
    const float* b2 = (const float*)d_in[12];
    const float* W3 = (const float*)d_in[13];
    const float* b3 = (const float*)d_in[14];
    const float* gamma = (const float*)d_in[15];
    const float* beta  = (const float*)d_in[16];
    float* out = (float*)d_out;

    float *q, *k, *v, *sc, *cc, *y, *f1, *f2, *f3, *y2;
    cudaGetSymbolAddress((void**)&q,  g_q);
    cudaGetSymbolAddress((void**)&k,  g_k);
    cudaGetSymbolAddress((void**)&v,  g_v);
    cudaGetSymbolAddress((void**)&sc, g_scores);
    cudaGetSymbolAddress((void**)&cc, g_concat);
    cudaGetSymbolAddress((void**)&y,  g_y);
    cudaGetSymbolAddress((void**)&f1, g_f1);
    cudaGetSymbolAddress((void**)&f2, g_f2);
    cudaGetSymbolAddress((void**)&f3, g_f3);
    cudaGetSymbolAddress((void**)&y2, g_y2);

    const int TPB = 256;

    // 1) Q/K/V projections: [16384,512] = x @ W^T + b
    {
        dim3 grid(DDIM/128, MROWS/128, 1);
        gemm_kernel<128,128,8,8,8,true,false><<<grid, TPB>>>(
            x, Wq, bq, nullptr, q, MROWS, DDIM, DDIM, DDIM, DDIM, DDIM,
            0,0, 0,0, 0,0, 1, 1.f);
        gemm_kernel<128,128,8,8,8,true,false><<<grid, TPB>>>(
            x, Wk, bk, nullptr, k, MROWS, DDIM, DDIM, DDIM, DDIM, DDIM,
            0,0, 0,0, 0,0, 1, 1.f);
        gemm_kernel<128,128,8,8,8,true,false><<<grid, TPB>>>(
            x, Wv, bv, nullptr, v, MROWS, DDIM, DDIM, DDIM, DDIM, DDIM,
            0,0, 0,0, 0,0, 1, 1.f);
    }

    // 2) scores[b,h] = (q @ k^T) / 8 ; batched over z = b*H + h
    {
        dim3 grid(SS/128, SS/128, BB*HH);
        gemm_kernel<128,128,8,8,8,true,false><<<grid, TPB>>>(
            q, k, nullptr, nullptr, sc, SS, SS, DK, DDIM, DDIM, SS,
            (long)SS*DDIM, DK,          // A: b -> b*S*D, h -> h*64
            (long)SS*DDIM, DK,          // B: same layout
            (long)HH*SS*SS, (long)SS*SS,// C: b -> b*H*S*S, h -> h*S*S
            HH, 0.125f);
    }

    // 3) softmax rows
    softmax_kernel<<<BB*HH*SS, 128>>>(sc);

    // 4) concat[b,h] = attn @ v   (non-transposed B)
    {
        dim3 grid(DK/64, SS/128, BB*HH);
        gemm_kernel<128,64,8,8,4,false,false><<<grid, TPB>>>(
            sc, v, nullptr, nullptr, cc, SS, DK, SS, SS, DDIM, DDIM,
            (long)HH*SS*SS, (long)SS*SS,
            (long)SS*DDIM, DK,
            (long)SS*DDIM, DK,
            HH, 1.f);
    }

    // 5) y = concat @ Wo^T + bo + x
    {
        dim3 grid(DDIM/128, MROWS/128, 1);
        gemm_kernel<128,128,8,8,8,true,false><<<grid, TPB>>>(
            cc, Wo, bo, x, y, MROWS, DDIM, DDIM, DDIM, DDIM, DDIM,
            0,0, 0,0, 0,0, 1, 1.f);
    }

    // 6) y = LN(y) (in-place)
    layernorm_kernel<<<BB, 1024>>>(y, nullptr, gamma, beta, y);

    // 7) f1 = relu(y @ W1^T + b1) : N=200
    {
        dim3 grid(2, MROWS/128, 1);
        gemm_kernel<128,128,8,8,8,true,true><<<grid, TPB>>>(
            y, W1, b1, nullptr, f1, MROWS, FFW, DDIM, DDIM, DDIM, FFW,
            0,0, 0,0, 0,0, 1, 1.f);
    }
    // 8) f2 = relu(f1 @ W2^T + b2) : K=200, N=200
    {
        dim3 grid(2, MROWS/128, 1);
        gemm_kernel<128,128,8,8,8,true,true><<<grid, TPB>>>(
            f1, W2, b2, nullptr, f2, MROWS, FFW, FFW, FFW, FFW, FFW,
            0,0, 0,0, 0,0, 1, 1.f);
    }
    // 9) f3 = f2 @ W3^T + b3 : K=200, N=512
    {
        dim3 grid(DDIM/128, MROWS/128, 1);
        gemm_kernel<128,128,8,8,8,true,false><<<grid, TPB>>>(
            f2, W3, b3, nullptr, f3, MROWS, DDIM, FFW, FFW, FFW, DDIM,
            0,0, 0,0, 0,0, 1, 1.f);
    }

    // 10) y2 = LN(f3 + y)
    layernorm_kernel<<<BB, 1024>>>(f3, y, gamma, beta, y2);

    // 11) out = LN(y2)
    layernorm_kernel<<<BB, 1024>>>(y2, nullptr, gamma, beta, out);
}

// round 3
// speedup vs baseline: 1.1867x; 1.1867x over previous
#include <cuda_runtime.h>

// Problem dims
#define BB   32
#define SS   512
#define DDIM 512
#define HH   8
#define DK   64
#define FFW  200
#define MROWS (BB * SS)          // 16384
#define LN_N  (SS * DDIM)        // 262144 elements per batch for 2-D LayerNorm

// ---------------- scratch (static device globals; no allocation) -------------
__device__ float g_q[MROWS * DDIM];
__device__ float g_k[MROWS * DDIM];
__device__ float g_v[MROWS * DDIM];
__device__ float g_scores[(long)BB * HH * SS * SS];   // 268 MB
__device__ float g_concat[MROWS * DDIM];
__device__ float g_y[MROWS * DDIM];
__device__ float g_f1[MROWS * FFW];
__device__ float g_f2[MROWS * FFW];
__device__ float g_f3[MROWS * DDIM];
__device__ float g_y2[MROWS * DDIM];

// ---------------- double-buffered tiled SGEMM --------------------------------
// C[m,n] = alpha * sum_k A[m,k] * B(n,k if TB else k,n)  (+bias[n]) (+Res) (relu?)
// Batch: z = blockIdx.z ; offsets via (z/zdiv, z%zdiv) strides.
// Requirements: M % BM == 0, K % BK == 0, BK % 4 == 0, N % 4 == 0, lda/ldb/ldc % 4 == 0.
template<int BM, int BN, int BK, int TM, int TN, bool TB, bool RELU>
__global__ __launch_bounds__((BM/TM)*(BN/TN), 2)
void gemm2(const float* __restrict__ A, const float* __restrict__ Bm,
           const float* __restrict__ bias, const float* __restrict__ Res,
           float* __restrict__ C,
           int M, int N, int K, int lda, int ldb, int ldc,
           long sA, long sA2, long sB, long sB2, long sC, long sC2,
           int zdiv, float alpha)
{
    constexpr int NT = (BM/TM)*(BN/TN);
    constexpr int LA = (BM*BK)/(NT*4);   // float4 loads per thread for A tile
    constexpr int LB = (BN*BK)/(NT*4);   // float4 loads per thread for B tile

    __shared__ float As[2][BK][BM];
    __shared__ float Bs[2][BK][BN];

    const int bz = blockIdx.z;
    const long zo1 = bz / zdiv, zo2 = bz % zdiv;
    A  += zo1 * sA + zo2 * sA2;
    Bm += zo1 * sB + zo2 * sB2;
    C  += zo1 * sC + zo2 * sC2;
    const float* Rp = Res ? (Res + zo1 * sC + zo2 * sC2) : nullptr;

    const int tid  = threadIdx.x;
    const int mBlk = blockIdx.y * BM;
    const int nBlk = blockIdx.x * BN;
    const int tr = tid / (BN/TN);
    const int tc = tid % (BN/TN);

    float acc[TM][TN] = {};
    float4 pa[LA], pb[LB];

    // ---- prologue: load tile 0 into regs ----
    #pragma unroll
    for (int j = 0; j < LA; j++) {
        int i = (tid + j*NT)*4, r = i / BK, kk = i % BK;
        pa[j] = *reinterpret_cast<const float4*>(&A[(long)(mBlk + r)*lda + kk]);
    }
    #pragma unroll
    for (int j = 0; j < LB; j++) {
        if (TB) {
            int i = (tid + j*NT)*4, r = i / BK, kk = i % BK;
            int gn = nBlk + r;
            pb[j] = (gn < N) ? *reinterpret_cast<const float4*>(&Bm[(long)gn*ldb + kk])
                             : make_float4(0.f, 0.f, 0.f, 0.f);
        } else {
            int i = (tid + j*NT)*4, kk = i / BN, n = i % BN;
            pb[j] = *reinterpret_cast<const float4*>(&Bm[(long)kk*ldb + nBlk + n]);
        }
    }
    // ---- store tile 0 into buffer 0 ----
    #pragma unroll
    for (int j = 0; j < LA; j++) {
        int i = (tid + j*NT)*4, r = i / BK, kk = i % BK;
        As[0][kk+0][r] = pa[j].x; As[0][kk+1][r] = pa[j].y;
        As[0][kk+2][r] = pa[j].z; As[0][kk+3][r] = pa[j].w;
    }
    #pragma unroll
    for (int j = 0; j < LB; j++) {
        if (TB) {
            int i = (tid + j*NT)*4, r = i / BK, kk = i % BK;
            Bs[0][kk+0][r] = pb[j].x; Bs[0][kk+1][r] = pb[j].y;
            Bs[0][kk+2][r] = pb[j].z; Bs[0][kk+3][r] = pb[j].w;
        } else {
            int i = (tid + j*NT)*4, kk = i / BN, n = i % BN;
            *reinterpret_cast<float4*>(&Bs[0][kk][n]) = pb[j];
        }
    }
    __syncthreads();

    const int nt = K / BK;
    for (int t = 0; t < nt; t++) {
        const int cur = t & 1, nxt = cur ^ 1;

        // ---- prefetch tile t+1 into registers (overlaps with compute below) ----
        if (t + 1 < nt) {
            const int kt = (t + 1) * BK;
            #pragma unroll
            for (int j = 0; j < LA; j++) {
                int i = (tid + j*NT)*4, r = i / BK, kk = i % BK;
                pa[j] = *reinterpret_cast<const float4*>(&A[(long)(mBlk + r)*lda + kt + kk]);
            }
            #pragma unroll
            for (int j = 0; j < LB; j++) {
                if (TB) {
                    int i = (tid + j*NT)*4, r = i / BK, kk = i % BK;
                    int gn = nBlk + r;
                    pb[j] = (gn < N) ? *reinterpret_cast<const float4*>(&Bm[(long)gn*ldb + kt + kk])
                                     : make_float4(0.f, 0.f, 0.f, 0.f);
                } else {
                    int i = (tid + j*NT)*4, kk = i / BN, n = i % BN;
                    pb[j] = *reinterpret_cast<const float4*>(&Bm[(long)(kt + kk)*ldb + nBlk + n]);
                }
            }
        }

        // ---- compute on current buffer ----
        #pragma unroll
        for (int kk = 0; kk < BK; kk++) {
            float rm[TM], rn[TN];
            *reinterpret_cast<float4*>(&rm[0]) =
                *reinterpret_cast<const float4*>(&As[cur][kk][tr*TM]);
            if (TM > 4)
                *reinterpret_cast<float4*>(&rm[4]) =
                    *reinterpret_cast<const float4*>(&As[cur][kk][tr*TM + 4]);
            *reinterpret_cast<float4*>(&rn[0]) =
                *reinterpret_cast<const float4*>(&Bs[cur][kk][tc*TN]);
            if (TN > 4)
                *reinterpret_cast<float4*>(&rn[4]) =
                    *reinterpret_cast<const float4*>(&Bs[cur][kk][tc*TN + 4]);
            #pragma unroll
            for (int i = 0; i < TM; i++)
                #pragma unroll
                for (int j = 0; j < TN; j++)
                    acc[i][j] += rm[i] * rn[j];
        }

        // ---- commit prefetched tile into the other buffer ----
        if (t + 1 < nt) {
            #pragma unroll
            for (int j = 0; j < LA; j++) {
                int i = (tid + j*NT)*4, r = i / BK, kk = i % BK;
                As[nxt][kk+0][r] = pa[j].x; As[nxt][kk+1][r] = pa[j].y;
                As[nxt][kk+2][r] = pa[j].z; As[nxt][kk+3][r] = pa[j].w;
            }
            #pragma unroll
            for (int j = 0; j < LB; j++) {
                if (TB) {
                    int i = (tid + j*NT)*4, r = i / BK, kk = i % BK;
                    Bs[nxt][kk+0][r] = pb[j].x; Bs[nxt][kk+1][r] = pb[j].y;
                    Bs[nxt][kk+2][r] = pb[j].z; Bs[nxt][kk+3][r] = pb[j].w;
                } else {
                    int i = (tid + j*NT)*4, kk = i / BN, n = i % BN;
                    *reinterpret_cast<float4*>(&Bs[nxt][kk][n]) = pb[j];
                }
            }
            __syncthreads();
        }
    }

    // ---- epilogue (float4 stores) ----
    const int rowBase = mBlk + tr*TM;
    const int colBase = nBlk + tc*TN;
    #pragma unroll
    for (int i = 0; i < TM; i++) {
        const long ro = (long)(rowBase + i) * ldc;
        #pragma unroll
        for (int j0 = 0; j0 < TN; j0 += 4) {
            const int gc = colBase + j0;
            if (gc < N) {
                float4 v;
                v.x = acc[i][j0+0] * alpha;
                v.y = acc[i][j0+1] * alpha;
                v.z = acc[i][j0+2] * alpha;
                v.w = acc[i][j0+3] * alpha;
                if (bias) {
                    float4 bb = *reinterpret_cast<const float4*>(&bias[gc]);
                    v.x += bb.x; v.y += bb.y; v.z += bb.z; v.w += bb.w;
                }
                if (Rp) {
                    float4 rr = *reinterpret_cast<const float4*>(&Rp[ro + gc]);
                    v.x += rr.x; v.y += rr.y; v.z += rr.z; v.w += rr.w;
                }
                if (RELU) {
                    v.x = fmaxf(v.x, 0.f); v.y = fmaxf(v.y, 0.f);
                    v.z = fmaxf(v.z, 0.f); v.w = fmaxf(v.w, 0.f);
                }
                *reinterpret_cast<float4*>(&C[ro + gc]) = v;
            }
        }
    }
}

// ---------------- row softmax over width 512 ----------------------------------
__global__ __launch_bounds__(128)
void softmax_kernel(float* __restrict__ sc)
{
    __shared__ float red[4];
    const long row = blockIdx.x;
    float4* p = reinterpret_cast<float4*>(sc) + row * 128 + threadIdx.x;
    float4 v = *p;
    const int lane = threadIdx.x & 31, wid = threadIdx.x >> 5;

    float m = fmaxf(fmaxf(v.x, v.y), fmaxf(v.z, v.w));
    #pragma unroll
    for (int o = 16; o; o >>= 1) m = fmaxf(m, __shfl_xor_sync(0xffffffffu, m, o));
    if (!lane) red[wid] = m;
    __syncthreads();
    m = fmaxf(fmaxf(red[0], red[1]), fmaxf(red[2], red[3]));
    __syncthreads();

    v.x = __expf(v.x - m); v.y = __expf(v.y - m);
    v.z = __expf(v.z - m); v.w = __expf(v.w - m);
    float s = (v.x + v.y) + (v.z + v.w);
    #pragma unroll
    for (int o = 16; o; o >>= 1) s += __shfl_xor_sync(0xffffffffu, s, o);
    if (!lane) red[wid] = s;
    __syncthreads();
    s = (red[0] + red[1]) + (red[2] + red[3]);

    const float inv = 1.f / s;
    v.x *= inv; v.y *= inv; v.z *= inv; v.w *= inv;
    *p = v;
}

// ---------------- 2-D LayerNorm over (S,D) per batch ---------------------------
__global__ __launch_bounds__(1024)
void layernorm_kernel(const float* __restrict__ X, const float* __restrict__ Add,
                      const float* __restrict__ gamma, const float* __restrict__ beta,
                      float* __restrict__ out)
{
    const long base = (long)blockIdx.x * LN_N;
    float s1 = 0.f, s2 = 0.f;
    for (int i = threadIdx.x*4; i < LN_N; i += 4096) {
        float4 v = *reinterpret_cast<const float4*>(X + base + i);
        if (Add) {
            float4 a = *reinterpret_cast<const float4*>(Add + base + i);
            v.x += a.x; v.y += a.y; v.z += a.z; v.w += a.w;
        }
        s1 += (v.x + v.y) + (v.z + v.w);
        s2 += (v.x*v.x + v.y*v.y) + (v.z*v.z + v.w*v.w);
    }
    __shared__ float r1[32], r2[32];
    const int lane = threadIdx.x & 31, wid = threadIdx.x >> 5;
    #pragma unroll
    for (int o = 16; o; o >>= 1) {
        s1 += __shfl_xor_sync(0xffffffffu, s1, o);
        s2 += __shfl_xor_sync(0xffffffffu, s2, o);
    }
    if (!lane) { r1[wid] = s1; r2[wid] = s2; }
    __syncthreads();
    if (threadIdx.x < 32) {
        s1 = r1[threadIdx.x]; s2 = r2[threadIdx.x];
        #pragma unroll
        for (int o = 16; o; o >>= 1) {
            s1 += __shfl_xor_sync(0xffffffffu, s1, o);
            s2 += __shfl_xor_sync(0xffffffffu, s2, o);
        }
        if (!threadIdx.x) { r1[0] = s1; r2[0] = s2; }
    }
    __syncthreads();
    const float mean = r1[0] / (float)LN_N;
    const float var  = r2[0] / (float)LN_N - mean * mean;
    const float rstd = rsqrtf(var + 1e-5f);

    for (int i = threadIdx.x*4; i < LN_N; i += 4096) {
        float4 v = *reinterpret_cast<const float4*>(X + base + i);
        if (Add) {
            float4 a = *reinterpret_cast<const float4*>(Add + base + i);
            v.x += a.x; v.y += a.y; v.z += a.z; v.w += a.w;
        }
        float4 g  = *reinterpret_cast<const float4*>(gamma + i);
        float4 bt = *reinterpret_cast<const float4*>(beta  + i);
        float4 o;
        o.x = (v.x - mean) * rstd * g.x + bt.x;
        o.y = (v.y - mean) * rstd * g.y + bt.y;
        o.z = (v.z - mean) * rstd * g.z + bt.z;
        o.w = (v.w - mean) * rstd * g.w + bt.w;
        *reinterpret_cast<float4*>(out + base + i) = o;
    }
}

// ---------------- launch --------------------------------------------------------
extern "C" void kernel_launch(void* const* d_in, const int* in_sizes, int n_in,
                              void* d_out, int out_size)
{
    const float* x  = (const float*)d_in[0];
    const float* Wq = (const float*)d_in[1];
    const float* bq = (const float*)d_in[2];
    const float* Wk = (const float*)d_in[3];
    const float* bk = (const float*)d_in[4];
    const float* Wv = (const float*)d_in[5];
    const float* bv = (const float*)d_in[6];
    const float* Wo = (const float*)d_in[7];
    const float* bo = (const float*)d_in[8];
    const float* W1 = (const float*)d_in[9];
    const float* b1 = (const float*)d_in[10];
    const float* W2 = (const float*)d_in[11];
    const float* b2 = (const float*)d_in[12];
    const float* W3 = (const float*)d_in[13];
    const float* b3 = (const float*)d_in[14];
    const float* gamma = (const float*)d_in[15];
    const float* beta  = (const float*)d_in[16];
    float* out = (float*)d_out;

    float *q, *k, *v, *sc, *cc, *y, *f1, *f2, *f3, *y2;
    cudaGetSymbolAddress((void**)&q,  g_q);
    cudaGetSymbolAddress((void**)&k,  g_k);
    cudaGetSymbolAddress((void**)&v,  g_v);
    cudaGetSymbolAddress((void**)&sc, g_scores);
    cudaGetSymbolAddress((void**)&cc, g_concat);
    cudaGetSymbolAddress((void**)&y,  g_y);
    cudaGetSymbolAddress((void**)&f1, g_f1);
    cudaGetSymbolAddress((void**)&f2, g_f2);
    cudaGetSymbolAddress((void**)&f3, g_f3);
    cudaGetSymbolAddress((void**)&y2, g_y2);

    const int TPB = 256;

    // 1) Q/K/V projections: [16384,512] = x @ W^T + b   (K=512, BK=16)
    {
        dim3 grid(DDIM/128, MROWS/128, 1);
        gemm2<128,128,16,8,8,true,false><<<grid, TPB>>>(
            x, Wq, bq, nullptr, q, MROWS, DDIM, DDIM, DDIM, DDIM, DDIM,
            0,0, 0,0, 0,0, 1, 1.f);
        gemm2<128,128,16,8,8,true,false><<<grid, TPB>>>(
            x, Wk, bk, nullptr, k, MROWS, DDIM, DDIM, DDIM, DDIM, DDIM,
            0,0, 0,0, 0,0, 1, 1.f);
        gemm2<128,128,16,8,8,true,false><<<grid, TPB>>>(
            x, Wv, bv, nullptr, v, MROWS, DDIM, DDIM, DDIM, DDIM, DDIM,
            0,0, 0,0, 0,0, 1, 1.f);
    }

    // 2) scores[b,h] = (q @ k^T) / 8 ; batched over z = b*H + h  (K=64, BK=16)
    {
        dim3 grid(SS/128, SS/128, BB*HH);
        gemm2<128,128,16,8,8,true,false><<<grid, TPB>>>(
            q, k, nullptr, nullptr, sc, SS, SS, DK, DDIM, DDIM, SS,
            (long)SS*DDIM, DK,
            (long)SS*DDIM, DK,
            (long)HH*SS*SS, (long)SS*SS,
            HH, 0.125f);
    }

    // 3) softmax rows
    softmax_kernel<<<BB*HH*SS, 128>>>(sc);

    // 4) concat[b,h] = attn @ v   (non-transposed B, K=512, BK=16, BN=64)
    {
        dim3 grid(1, SS/128, BB*HH);
        gemm2<128,64,16,8,4,false,false><<<grid, TPB>>>(
            sc, v, nullptr, nullptr, cc, SS, DK, SS, SS, DDIM, DDIM,
            (long)HH*SS*SS, (long)SS*SS,
            (long)SS*DDIM, DK,
            (long)SS*DDIM, DK,
            HH, 1.f);
    }

    // 5) y = concat @ Wo^T + bo + x  (K=512, BK=16)
    {
        dim3 grid(DDIM/128, MROWS/128, 1);
        gemm2<128,128,16,8,8,true,false><<<grid, TPB>>>(
            cc, Wo, bo, x, y, MROWS, DDIM, DDIM, DDIM, DDIM, DDIM,
            0,0, 0,0, 0,0, 1, 1.f);
    }

    // 6) y = LN(y) (in-place)
    layernorm_kernel<<<BB, 1024>>>(y, nullptr, gamma, beta, y);

    // 7) f1 = relu(y @ W1^T + b1) : N=200, K=512 (BK=16)
    {
        dim3 grid(2, MROWS/128, 1);
        gemm2<128,128,16,8,8,true,true><<<grid, TPB>>>(
            y, W1, b1, nullptr, f1, MROWS, FFW, DDIM, DDIM, DDIM, FFW,
            0,0, 0,0, 0,0, 1, 1.f);
    }
    // 8) f2 = relu(f1 @ W2^T + b2) : K=200 (BK=8), N=200
    {
        dim3 grid(2, MROWS/128, 1);
        gemm2<128,128,8,8,8,true,true><<<grid, TPB>>>(
            f1, W2, b2, nullptr, f2, MROWS, FFW, FFW, FFW, FFW, FFW,
            0,0, 0,0, 0,0, 1, 1.f);
    }
    // 9) f3 = f2 @ W3^T + b3 : K=200 (BK=8), N=512
    {
        dim3 grid(DDIM/128, MROWS/128, 1);
        gemm2<128,128,8,8,8,true,false><<<grid, TPB>>>(
            f2, W3, b3, nullptr, f3, MROWS, DDIM, FFW, FFW, FFW, DDIM,
            0,0, 0,0, 0,0, 1, 1.f);
    }

    // 10) y2 = LN(f3 + y)
    layernorm_kernel<<<BB, 1024>>>(f3, y, gamma, beta, y2);

    // 11) out = LN(y2)
    layernorm_kernel<<<BB, 1024>>>(y2, nullptr, gamma, beta, out);
}

// round 7
// speedup vs baseline: 2.0715x; 1.7456x over previous
#include <cuda_runtime.h>
#include <cuda_bf16.h>
#include <cstdint>

// ---------------- problem dims ------------------------------------------------
#define NB   32
#define NS   512
#define ND   512
#define NH   8
#define NDK  64
#define NFF  200
#define NFP  256            // padded FF width
#define NM   (NB * NS)      // 16384 rows
#define LN_N (NS * ND)      // 262144 elems per batch for 2-D LayerNorm

// ---------------- arena (single static device allocation) ---------------------
constexpr size_t SZ_BF_MD = (size_t)NM * ND * 2;        // [16384,512] bf16
constexpr size_t SZ_BF_DD = (size_t)ND * ND * 2;        // [512,512]  bf16
constexpr size_t SZ_BF_W1 = (size_t)NFP * ND * 2;
constexpr size_t SZ_BF_W2 = (size_t)NFP * NFP * 2;
constexpr size_t SZ_BF_W3 = (size_t)ND * NFP * 2;
constexpr size_t SZ_F_SC  = (size_t)NB * NH * NS * NS * 4;
constexpr size_t SZ_BF_SC = (size_t)NB * NH * NS * NS * 2;
constexpr size_t SZ_F_MD  = (size_t)NM * ND * 4;
constexpr size_t SZ_BF_MF = (size_t)NM * NFP * 2;

constexpr size_t O_XH = 0,                 O_XL = O_XH + SZ_BF_MD;
constexpr size_t O_WQH = O_XL + SZ_BF_MD,  O_WQL = O_WQH + SZ_BF_DD;
constexpr size_t O_WKH = O_WQL + SZ_BF_DD, O_WKL = O_WKH + SZ_BF_DD;
constexpr size_t O_WVH = O_WKL + SZ_BF_DD, O_WVL = O_WVH + SZ_BF_DD;
constexpr size_t O_WOH = O_WVL + SZ_BF_DD, O_WOL = O_WOH + SZ_BF_DD;
constexpr size_t O_W1H = O_WOL + SZ_BF_DD, O_W1L = O_W1H + SZ_BF_W1;
constexpr size_t O_W2H = O_W1L + SZ_BF_W1, O_W2L = O_W2H + SZ_BF_W2;
constexpr size_t O_W3H = O_W2L + SZ_BF_W2, O_W3L = O_W3H + SZ_BF_W3;
constexpr size_t O_B1P = O_W3L + SZ_BF_W3, O_B2P = O_B1P + 1024;
constexpr size_t O_QH  = O_B2P + 1024,     O_QL  = O_QH + SZ_BF_MD;
constexpr size_t O_KH  = O_QL + SZ_BF_MD,  O_KL  = O_KH + SZ_BF_MD;
constexpr size_t O_VTH = O_KL + SZ_BF_MD,  O_VTL = O_VTH + SZ_BF_MD;
constexpr size_t O_SC  = O_VTL + SZ_BF_MD;
constexpr size_t O_ATH = O_SC + SZ_F_SC,   O_ATL = O_ATH + SZ_BF_SC;
constexpr size_t O_CCH = O_ATL + SZ_BF_SC, O_CCL = O_CCH + SZ_BF_MD;
constexpr size_t O_Y   = O_CCL + SZ_BF_MD;
constexpr size_t O_YH  = O_Y + SZ_F_MD,    O_YL  = O_YH + SZ_BF_MD;
constexpr size_t O_F1H = O_YL + SZ_BF_MD,  O_F1L = O_F1H + SZ_BF_MF;
constexpr size_t O_F2H = O_F1L + SZ_BF_MF, O_F2L = O_F2H + SZ_BF_MF;
constexpr size_t O_F3  = O_F2L + SZ_BF_MF;
constexpr size_t O_Y2  = O_F3 + SZ_F_MD;
constexpr size_t ARENA = O_Y2 + SZ_F_MD;

__device__ __align__(1024) unsigned char g_arena[ARENA];

// ---------------- helpers -----------------------------------------------------
__device__ __forceinline__ uint32_t su32(const void* p) {
    uint32_t a;
    asm("{ .reg .u64 t; cvta.to.shared.u64 t, %1; cvt.u32.u64 %0, t; }" : "=r"(a) : "l"(p));
    return a;
}
__device__ __forceinline__ void cpa16(uint32_t d, const void* s) {
    asm volatile("cp.async.ca.shared.global [%0], [%1], 16;" :: "r"(d), "l"(s));
}
__device__ __forceinline__ void cp_commit() {
    asm volatile("cp.async.commit_group;" ::: "memory");
}
__device__ __forceinline__ void ldm4(uint32_t* r, uint32_t a) {
    asm volatile("ldmatrix.sync.aligned.m8n8.x4.shared.b16 {%0,%1,%2,%3}, [%4];"
        : "=r"(r[0]), "=r"(r[1]), "=r"(r[2]), "=r"(r[3]) : "r"(a));
}
__device__ __forceinline__ void mma16816(float* c, const uint32_t* a, uint32_t b0, uint32_t b1) {
    asm volatile("mma.sync.aligned.m16n8k16.row.col.f32.bf16.bf16.f32 "
        "{%0,%1,%2,%3}, {%4,%5,%6,%7}, {%8,%9}, {%0,%1,%2,%3};"
        : "+f"(c[0]), "+f"(c[1]), "+f"(c[2]), "+f"(c[3])
        : "r"(a[0]), "r"(a[1]), "r"(a[2]), "r"(a[3]), "r"(b0), "r"(b1));
}
__device__ __forceinline__ void split2(float v, __nv_bfloat16& h, __nv_bfloat16& l) {
    h = __float2bfloat16(v);
    l = __float2bfloat16(v - __bfloat162float(h));
}
__device__ __forceinline__ uint32_t pack2(__nv_bfloat16 a, __nv_bfloat16 b) {
    return (uint32_t)__bfloat16_as_ushort(a) | ((uint32_t)__bfloat16_as_ushort(b) << 16);
}

// ---------------- bf16 HMMA GEMM: D[M,N] = Ahi/lo @ Bhi/lo^T (3-product fp32 emu)
// A is [M][K] row-major (lda), B is [N][K] row-major (ldb); both as hi/lo pairs.
// MODE 0: f32 out (+bias)(+Res)   MODE 1: bf16 pair out (+bias)(RELU)(alpha)
// MODE 2: bf16 pair out in v-transposed layout vt[(b*512+n)*512+t]
// Block: 128 x BN, K-step 32, 512 threads, 2-stage cp.async pipeline.
template<int BN, int MODE, bool RELU>
__global__ __launch_bounds__(512, 1)
void gemm_mma(const __nv_bfloat16* __restrict__ Ah, const __nv_bfloat16* __restrict__ Al,
              const __nv_bfloat16* __restrict__ Bh, const __nv_bfloat16* __restrict__ Bl,
              const float* __restrict__ bias, const float* __restrict__ Res,
              float* __restrict__ Cf, __nv_bfloat16* __restrict__ Chi, __nv_bfloat16* __restrict__ Clo,
              int K, int lda, int ldb, int ldc,
              long sA, long sA2, long sB, long sB2, long sC, long sC2,
              int zdiv, float alpha)
{
    constexpr int WGN = BN / 32;          // warps along N
    constexpr int WGM = 16 / WGN;         // warps along M
    constexpr int WTM = 128 / WGM;        // warp tile M (32 or 16)
    constexpr int MT  = WTM / 16;         // m16 tiles per warp (2 or 1)
    constexpr int LDS = 40;               // smem row stride in halves (conflict-free pad)
    constexpr int A_H = 128 * LDS;        // halves per A buffer
    constexpr int B_H = BN * LDS;         // halves per B buffer
    constexpr int STG = 2 * A_H + 2 * B_H;

    extern __shared__ __align__(16) __nv_bfloat16 sm[];
    const uint32_t sb = su32(sm);

    const int tid = threadIdx.x, wid = tid >> 5, lane = tid & 31;
    const int wn = wid % WGN, wm = wid / WGN;

    const int bz = blockIdx.z;
    const long zo1 = bz / zdiv, zo2 = bz % zdiv;
    Ah += zo1 * sA + zo2 * sA2;  Al += zo1 * sA + zo2 * sA2;
    Bh += zo1 * sB + zo2 * sB2;  Bl += zo1 * sB + zo2 * sB2;
    const long coff = zo1 * sC + zo2 * sC2;

    const int mBlk = blockIdx.y * 128, nBlk = blockIdx.x * BN;
    Ah += (long)mBlk * lda; Al += (long)mBlk * lda;
    Bh += (long)nBlk * ldb; Bl += (long)nBlk * ldb;

    // ---- stage copy via cp.async ----
    auto stage_copy = [&](int t, int s) {
        const int kt = t * 32;
        const uint32_t st = sb + 2u * (uint32_t)(s * STG);
        for (int i = tid; i < 128 * 4; i += 512) {
            const int r = i >> 2, cg = (i & 3) * 8;
            const long go = (long)r * lda + kt + cg;
            const uint32_t d = st + 2u * (uint32_t)(r * LDS + cg);
            cpa16(d,             Ah + go);
            cpa16(d + 2u * A_H,  Al + go);
        }
        for (int i = tid; i < BN * 4; i += 512) {
            const int r = i >> 2, cg = (i & 3) * 8;
            const long go = (long)r * ldb + kt + cg;
            const uint32_t d = st + 2u * (uint32_t)(2 * A_H + r * LDS + cg);
            cpa16(d,             Bh + go);
            cpa16(d + 2u * B_H,  Bl + go);
        }
        cp_commit();
    };

    float acc[MT][4][4];
    #pragma unroll
    for (int i = 0; i < MT; i++)
        #pragma unroll
        for (int j = 0; j < 4; j++)
            #pragma unroll
            for (int q = 0; q < 4; q++) acc[i][j][q] = 0.f;

    const int nt = K / 32;
    stage_copy(0, 0);

    for (int t = 0; t < nt; t++) {
        if (t + 1 < nt) stage_copy(t + 1, (t + 1) & 1);
        if (t + 1 < nt) asm volatile("cp.async.wait_group 1;" ::: "memory");
        else            asm volatile("cp.async.wait_group 0;" ::: "memory");
        __syncthreads();

        const int s = t & 1;
        const uint32_t ab = sb + 2u * (uint32_t)(s * STG);
        const uint32_t bb = ab + 2u * (uint32_t)(2 * A_H);
        const int arow = wm * WTM + (lane & 15);
        const int bmat = lane >> 3, bmr = lane & 7;

        #pragma unroll
        for (int ks = 0; ks < 2; ks++) {
            const int acol = ks * 16 + (lane >> 4) * 8;
            uint32_t afh[MT][4], afl[MT][4];
            #pragma unroll
            for (int mt = 0; mt < MT; mt++) {
                const uint32_t ad = ab + 2u * (uint32_t)((arow + mt * 16) * LDS + acol);
                ldm4(afh[mt], ad);
                ldm4(afl[mt], ad + 2u * A_H);
            }
            uint32_t bfh[8], bfl[8];
            #pragma unroll
            for (int p = 0; p < 2; p++) {
                const int n = wn * 32 + (p * 2 + (bmat >> 1)) * 8 + bmr;
                const int koff = ks * 16 + (bmat & 1) * 8;
                const uint32_t bd = bb + 2u * (uint32_t)(n * LDS + koff);
                ldm4(&bfh[p * 4], bd);
                ldm4(&bfl[p * 4], bd + 2u * B_H);
            }
            #pragma unroll
            for (int mt = 0; mt < MT; mt++) {
                #pragma unroll
                for (int n4 = 0; n4 < 4; n4++) {
                    const int bi = (n4 >> 1) * 4 + (n4 & 1) * 2;
                    mma16816(acc[mt][n4], afh[mt], bfh[bi], bfh[bi + 1]);
                    mma16816(acc[mt][n4], afh[mt], bfl[bi], bfl[bi + 1]);
                    mma16816(acc[mt][n4], afl[mt], bfh[bi], bfh[bi + 1]);
                }
            }
        }
        __syncthreads();
    }

    // ---- epilogue ----
    const int mBase = mBlk + wm * WTM + (lane >> 2);
    const int nBase = nBlk + wn * 32 + (lane & 3) * 2;
    #pragma unroll
    for (int mt = 0; mt < MT; mt++) {
        #pragma unroll
        for (int n4 = 0; n4 < 4; n4++) {
            const int n0 = nBase + n4 * 8;
            float bx = 0.f, by = 0.f;
            if (bias) { bx = bias[n0]; by = bias[n0 + 1]; }
            #pragma unroll
            for (int half = 0; half < 2; half++) {
                const int m = mBase + mt * 16 + half * 8;
                float v0 = acc[mt][n4][half * 2 + 0] + bx;
                float v1 = acc[mt][n4][half * 2 + 1] + by;
                v0 *= alpha; v1 *= alpha;
                if (RELU) { v0 = fmaxf(v0, 0.f); v1 = fmaxf(v1, 0.f); }
                if (MODE == 0) {
                    const long ro = coff + (long)m * ldc + n0;
                    if (Res) { v0 += Res[ro]; v1 += Res[ro + 1]; }
                    *reinterpret_cast<float2*>(Cf + ro) = make_float2(v0, v1);
                } else if (MODE == 1) {
                    const long ro = coff + (long)m * ldc + n0;
                    __nv_bfloat16 h0, h1, l0, l1;
                    split2(v0, h0, l0); split2(v1, h1, l1);
                    *reinterpret_cast<uint32_t*>(Chi + ro) = pack2(h0, h1);
                    *reinterpret_cast<uint32_t*>(Clo + ro) = pack2(l0, l1);
                } else {   // MODE 2: vt[(b*512 + n)*512 + t]
                    const int bq = m >> 9, tq = m & 511;
                    __nv_bfloat16 h0, h1, l0, l1;
                    split2(v0, h0, l0); split2(v1, h1, l1);
                    const long a0 = ((long)(bq * 512 + n0)) * 512 + tq;
                    const long a1 = a0 + 512;
                    Chi[a0] = h0; Clo[a0] = l0;
                    Chi[a1] = h1; Clo[a1] = l1;
                }
            }
        }
    }
}

// ---------------- fp32 -> bf16 hi/lo split with zero-padding -------------------
__global__ void split_kernel(const float* __restrict__ src, __nv_bfloat16* __restrict__ hi,
                             __nv_bfloat16* __restrict__ lo, int rs, int cs, int rd, int cd)
{
    const long idx4 = ((long)blockIdx.x * blockDim.x + threadIdx.x) * 4;
    if (idx4 >= (long)rd * cd) return;
    const int r = (int)(idx4 / cd), c = (int)(idx4 % cd);
    float4 v = make_float4(0.f, 0.f, 0.f, 0.f);
    if (r < rs && c < cs) v = *reinterpret_cast<const float4*>(src + (long)r * cs + c);
    __nv_bfloat16 h0, h1, h2, h3, l0, l1, l2, l3;
    split2(v.x, h0, l0); split2(v.y, h1, l1); split2(v.z, h2, l2); split2(v.w, h3, l3);
    *reinterpret_cast<uint2*>(hi + idx4) = make_uint2(pack2(h0, h1), pack2(h2, h3));
    *reinterpret_cast<uint2*>(lo + idx4) = make_uint2(pack2(l0, l1), pack2(l2, l3));
}

__global__ void pad_bias(const float* __restrict__ s, float* __restrict__ d, int n) {
    const int i = threadIdx.x;
    d[i] = (i < n) ? s[i] : 0.f;
}

// ---------------- row softmax (width 512) -> bf16 hi/lo ------------------------
__global__ __launch_bounds__(128)
void softmax_pair(const float* __restrict__ sc, __nv_bfloat16* __restrict__ ah,
                  __nv_bfloat16* __restrict__ al)
{
    __shared__ float red[4];
    const long row = blockIdx.x;
    const float4* p = reinterpret_cast<const float4*>(sc) + row * 128 + threadIdx.x;
    float4 v = *p;
    const int lane = threadIdx.x & 31, wid = threadIdx.x >> 5;

    float m = fmaxf(fmaxf(v.x, v.y), fmaxf(v.z, v.w));
    #pragma unroll
    for (int o = 16; o; o >>= 1) m = fmaxf(m, __shfl_xor_sync(0xffffffffu, m, o));
    if (!lane) red[wid] = m;
    __syncthreads();
    m = fmaxf(fmaxf(red[0], red[1]), fmaxf(red[2], red[3]));
    __syncthreads();

    v.x = __expf(v.x - m); v.y = __expf(v.y - m);
    v.z = __expf(v.z - m); v.w = __expf(v.w - m);
    float s = (v.x + v.y) + (v.z + v.w);
    #pragma unroll
    for (int o = 16; o; o >>= 1) s += __shfl_xor_sync(0xffffffffu, s, o);
    if (!lane) red[wid] = s;
    __syncthreads();
    s = (red[0] + red[1]) + (red[2] + red[3]);
    const float inv = 1.f / s;
    v.x *= inv; v.y *= inv; v.z *= inv; v.w *= inv;

    __nv_bfloat16 h0, h1, h2, h3, l0, l1, l2, l3;
    split2(v.x, h0, l0); split2(v.y, h1, l1); split2(v.z, h2, l2); split2(v.w, h3, l3);
    reinterpret_cast<uint2*>(ah + row * 512)[threadIdx.x] = make_uint2(pack2(h0, h1), pack2(h2, h3));
    reinterpret_cast<uint2*>(al + row * 512)[threadIdx.x] = make_uint2(pack2(l0, l1), pack2(l2, l3));
}

// ---------------- 2-D LayerNorm over (S,D) per batch ---------------------------
template<bool PAIR>
__global__ __launch_bounds__(1024)
void layernorm_kernel(const float* __restrict__ X, const float* __restrict__ Add,
                      const float* __restrict__ gamma, const float* __restrict__ beta,
                      float* __restrict__ out, __nv_bfloat16* __restrict__ oh,
                      __nv_bfloat16* __restrict__ ol)
{
    const long base = (long)blockIdx.x * LN_N;
    float s1 = 0.f, s2 = 0.f;
    for (int i = threadIdx.x * 4; i < LN_N; i += 4096) {
        float4 v = *reinterpret_cast<const float4*>(X + base + i);
        if (Add) {
            float4 a = *reinterpret_cast<const float4*>(Add + base + i);
            v.x += a.x; v.y += a.y; v.z += a.z; v.w += a.w;
        }
        s1 += (v.x + v.y) + (v.z + v.w);
        s2 += (v.x*v.x + v.y*v.y) + (v.z*v.z + v.w*v.w);
    }
    __shared__ float r1[32], r2[32];
    const int lane = threadIdx.x & 31, wid = threadIdx.x >> 5;
    #pragma unroll
    for (int o = 16; o; o >>= 1) {
        s1 += __shfl_xor_sync(0xffffffffu, s1, o);
        s2 += __shfl_xor_sync(0xffffffffu, s2, o);
    }
    if (!lane) { r1[wid] = s1; r2[wid] = s2; }
    __syncthreads();
    if (threadIdx.x < 32) {
        s1 = r1[threadIdx.x]; s2 = r2[threadIdx.x];
        #pragma unroll
        for (int o = 16; o; o >>= 1) {
            s1 += __shfl_xor_sync(0xffffffffu, s1, o);
            s2 += __shfl_xor_sync(0xffffffffu, s2, o);
        }
        if (!threadIdx.x) { r1[0] = s1; r2[0] = s2; }
    }
    __syncthreads();
    const float mean = r1[0] / (float)LN_N;
    const float var  = r2[0] / (float)LN_N - mean * mean;
    const float rstd = rsqrtf(var + 1e-5f);

    for (int i = threadIdx.x * 4; i < LN_N; i += 4096) {
        float4 v = *reinterpret_cast<const float4*>(X + base + i);
        if (Add) {
            float4 a = *reinterpret_cast<const float4*>(Add + base + i);
            v.x += a.x; v.y += a.y; v.z += a.z; v.w += a.w;
        }
        float4 g  = *reinterpret_cast<const float4*>(gamma + i);
        float4 bt = *reinterpret_cast<const float4*>(beta  + i);
        float4 o;
        o.x = (v.x - mean) * rstd * g.x + bt.x;
        o.y = (v.y - mean) * rstd * g.y + bt.y;
        o.z = (v.z - mean) * rstd * g.z + bt.z;
        o.w = (v.w - mean) * rstd * g.w + bt.w;
        *reinterpret_cast<float4*>(out + base + i) = o;
        if (PAIR) {
            __nv_bfloat16 h0, h1, h2, h3, l0, l1, l2, l3;
            split2(o.x, h0, l0); split2(o.y, h1, l1); split2(o.z, h2, l2); split2(o.w, h3, l3);
            *reinterpret_cast<uint2*>(oh + base + i) = make_uint2(pack2(h0, h1), pack2(h2, h3));
            *reinterpret_cast<uint2*>(ol + base + i) = make_uint2(pack2(l0, l1), pack2(l2, l3));
        }
    }
}

// ---------------- launch --------------------------------------------------------
extern "C" void kernel_launch(void* const* d_in, const int* in_sizes, int n_in,
                              void* d_out, int out_size)
{
    const float* x  = (const float*)d_in[0];
    const float* Wq = (const float*)d_in[1];
    const float* bq = (const float*)d_in[2];
    const float* Wk = (const float*)d_in[3];
    const float* bk = (const float*)d_in[4];
    const float* Wv = (const float*)d_in[5];
    const float* bv = (const float*)d_in[6];
    const float* Wo = (const float*)d_in[7];
    const float* bo = (const float*)d_in[8];
    const float* W1 = (const float*)d_in[9];
    const float* b1 = (const float*)d_in[10];
    const float* W2 = (const float*)d_in[11];
    const float* b2 = (const float*)d_in[12];
    const float* W3 = (const float*)d_in[13];
    const float* b3 = (const float*)d_in[14];
    const float* gamma = (const float*)d_in[15];
    const float* beta  = (const float*)d_in[16];
    float* out = (float*)d_out;

    unsigned char* ar;
    cudaGetSymbolAddress((void**)&ar, g_arena);
    #define BF(o) reinterpret_cast<__nv_bfloat16*>(ar + (o))
    #define FP(o) reinterpret_cast<float*>(ar + (o))

    // dynamic smem: 2 stages * (2*A + 2*B) halves * 2 bytes
    const int SM128 = 2 * (2 * 128 * 40 + 2 * 128 * 40) * 2;   // 81920
    const int SM64  = 2 * (2 * 128 * 40 + 2 * 64 * 40) * 2;    // 61440
    cudaFuncSetAttribute((const void*)gemm_mma<128, 0, false>, cudaFuncAttributeMaxDynamicSharedMemorySize, SM128);
    cudaFuncSetAttribute((const void*)gemm_mma<128, 1, false>, cudaFuncAttributeMaxDynamicSharedMemorySize, SM128);
    cudaFuncSetAttribute((const void*)gemm_mma<128, 1, true >, cudaFuncAttributeMaxDynamicSharedMemorySize, SM128);
    cudaFuncSetAttribute((const void*)gemm_mma<128, 2, false>, cudaFuncAttributeMaxDynamicSharedMemorySize, SM128);
    cudaFuncSetAttribute((const void*)gemm_mma<64,  1, false>, cudaFuncAttributeMaxDynamicSharedMemorySize, SM64);

    // ---- splits (fp32 -> bf16 hi/lo, with padding) ----
    auto g4 = [](long n) { return (unsigned)((n / 4 + 255) / 256); };
    split_kernel<<<g4((long)NM*ND),   256>>>(x,  BF(O_XH),  BF(O_XL),  NM, ND, NM, ND);
    split_kernel<<<g4((long)ND*ND),   256>>>(Wq, BF(O_WQH), BF(O_WQL), ND, ND, ND, ND);
    split_kernel<<<g4((long)ND*ND),   256>>>(Wk, BF(O_WKH), BF(O_WKL), ND, ND, ND, ND);
    split_kernel<<<g4((long)ND*ND),   256>>>(Wv, BF(O_WVH), BF(O_WVL), ND, ND, ND, ND);
    split_kernel<<<g4((long)ND*ND),   256>>>(Wo, BF(O_WOH), BF(O_WOL), ND, ND, ND, ND);
    split_kernel<<<g4((long)NFP*ND),  256>>>(W1, BF(O_W1H), BF(O_W1L), NFF, ND,  NFP, ND);
    split_kernel<<<g4((long)NFP*NFP), 256>>>(W2, BF(O_W2H), BF(O_W2L), NFF, NFF, NFP, NFP);
    split_kernel<<<g4((long)ND*NFP),  256>>>(W3, BF(O_W3H), BF(O_W3L), ND,  NFF, ND,  NFP);
    pad_bias<<<1, 256>>>(b1, FP(O_B1P), NFF);
    pad_bias<<<1, 256>>>(b2, FP(O_B2P), NFF);

    // ---- 1) Q/K/V projections (q pre-scaled by 1/8; v written transposed) ----
    {
        dim3 grid(4, 128, 1);
        gemm_mma<128, 1, false><<<grid, 512, SM128>>>(
            BF(O_XH), BF(O_XL), BF(O_WQH), BF(O_WQL), bq, nullptr,
            nullptr, BF(O_QH), BF(O_QL), ND, ND, ND, ND,
            0, 0, 0, 0, 0, 0, 1, 0.125f);
        gemm_mma<128, 1, false><<<grid, 512, SM128>>>(
            BF(O_XH), BF(O_XL), BF(O_WKH), BF(O_WKL), bk, nullptr,
            nullptr, BF(O_KH), BF(O_KL), ND, ND, ND, ND,
            0, 0, 0, 0, 0, 0, 1, 1.f);
        gemm_mma<128, 2, false><<<grid, 512, SM128>>>(
            BF(O_XH), BF(O_XL), BF(O_WVH), BF(O_WVL), bv, nullptr,
            nullptr, BF(O_VTH), BF(O_VTL), ND, ND, ND, ND,
            0, 0, 0, 0, 0, 0, 1, 1.f);
    }

    // ---- 2) scores = qs @ k^T (batched over b,h) ----
    {
        dim3 grid(4, 4, NB * NH);
        gemm_mma<128, 0, false><<<grid, 512, SM128>>>(
            BF(O_QH), BF(O_QL), BF(O_KH), BF(O_KL), nullptr, nullptr,
            FP(O_SC), nullptr, nullptr, NDK, ND, ND, NS,
            (long)NS * ND, NDK, (long)NS * ND, NDK,
            (long)NH * NS * NS, (long)NS * NS, NH, 1.f);
    }

    // ---- 3) softmax -> attn bf16 pair ----
    softmax_pair<<<NB * NH * NS, 128>>>(FP(O_SC), BF(O_ATH), BF(O_ATL));

    // ---- 4) heads = attn @ v  (B = v transposed) -> concat pair ----
    {
        dim3 grid(1, 4, NB * NH);
        gemm_mma<64, 1, false><<<grid, 512, SM64>>>(
            BF(O_ATH), BF(O_ATL), BF(O_VTH), BF(O_VTL), nullptr, nullptr,
            nullptr, BF(O_CCH), BF(O_CCL), NS, NS, NS, ND,
            (long)NH * NS * NS, (long)NS * NS,
            (long)NS * NS, (long)NDK * NS,
            (long)NS * ND, NDK, NH, 1.f);
    }

    // ---- 5) y = concat @ Wo^T + bo + x  (fp32) ----
    {
        dim3 grid(4, 128, 1);
        gemm_mma<128, 0, false><<<grid, 512, SM128>>>(
            BF(O_CCH), BF(O_CCL), BF(O_WOH), BF(O_WOL), bo, x,
            FP(O_Y), nullptr, nullptr, ND, ND, ND, ND,
            0, 0, 0, 0, 0, 0, 1, 1.f);
    }

    // ---- 6) y = LN(y), also emit bf16 pair ----
    layernorm_kernel<true><<<NB, 1024>>>(FP(O_Y), nullptr, gamma, beta,
                                         FP(O_Y), BF(O_YH), BF(O_YL));

    // ---- 7) f1 = relu(y @ W1p^T + b1p) pair, N=256 ----
    {
        dim3 grid(2, 128, 1);
        gemm_mma<128, 1, true><<<grid, 512, SM128>>>(
            BF(O_YH), BF(O_YL), BF(O_W1H), BF(O_W1L), FP(O_B1P), nullptr,
            nullptr, BF(O_F1H), BF(O_F1L), ND, ND, ND, NFP,
            0, 0, 0, 0, 0, 0, 1, 1.f);
    }
    // ---- 8) f2 = relu(f1 @ W2p^T + b2p) pair, K=N=256 ----
    {
        dim3 grid(2, 128, 1);
        gemm_mma<128, 1, true><<<grid, 512, SM128>>>(
            BF(O_F1H), BF(O_F1L), BF(O_W2H), BF(O_W2L), FP(O_B2P), nullptr,
            nullptr, BF(O_F2H), BF(O_F2L), NFP, NFP, NFP, NFP,
            0, 0, 0, 0, 0, 0, 1, 1.f);
    }
    // ---- 9) f3 = f2 @ W3p^T + b3 + y  (fp32, residual folded) ----
    {
        dim3 grid(4, 128, 1);
        gemm_mma<128, 0, false><<<grid, 512, SM128>>>(
            BF(O_F2H), BF(O_F2L), BF(O_W3H), BF(O_W3L), b3, FP(O_Y),
            FP(O_F3), nullptr, nullptr, NFP, NFP, NFP, ND,
            0, 0, 0, 0, 0, 0, 1, 1.f);
    }

    // ---- 10) y2 = LN(f3)  (f3 already includes +y) ----
    layernorm_kernel<false><<<NB, 1024>>>(FP(O_F3), nullptr, gamma, beta,
                                          FP(O_Y2), nullptr, nullptr);
    // ---- 11) out = LN(y2) ----
    layernorm_kernel<false><<<NB, 1024>>>(FP(O_Y2), nullptr, gamma, beta,
                                          out, nullptr, nullptr);
}

// round 8
// speedup vs baseline: 2.2653x; 1.0935x over previous
#include <cuda_runtime.h>
#include <cuda_bf16.h>
#include <cstdint>

// ---------------- problem dims ------------------------------------------------
#define NB   32
#define NS   512
#define ND   512
#define NH   8
#define NDK  64
#define NFF  200
#define NFP  256            // padded FF width
#define NM   (NB * NS)      // 16384 rows
#define LN_N (NS * ND)      // 262144 elems per batch for 2-D LayerNorm

// ---------------- arena (single static device allocation) ---------------------
constexpr size_t SZ_BF_MD = (size_t)NM * ND * 2;        // [16384,512] bf16
constexpr size_t SZ_BF_DD = (size_t)ND * ND * 2;        // [512,512]  bf16
constexpr size_t SZ_BF_W1 = (size_t)NFP * ND * 2;
constexpr size_t SZ_BF_W2 = (size_t)NFP * NFP * 2;
constexpr size_t SZ_BF_W3 = (size_t)ND * NFP * 2;
constexpr size_t SZ_F_MD  = (size_t)NM * ND * 4;
constexpr size_t SZ_BF_MF = (size_t)NM * NFP * 2;

constexpr size_t O_XH = 0,                 O_XL = O_XH + SZ_BF_MD;
constexpr size_t O_WQH = O_XL + SZ_BF_MD,  O_WQL = O_WQH + SZ_BF_DD;
constexpr size_t O_WKH = O_WQL + SZ_BF_DD, O_WKL = O_WKH + SZ_BF_DD;
constexpr size_t O_WVH = O_WKL + SZ_BF_DD, O_WVL = O_WVH + SZ_BF_DD;
constexpr size_t O_WOH = O_WVL + SZ_BF_DD, O_WOL = O_WOH + SZ_BF_DD;
constexpr size_t O_W1H = O_WOL + SZ_BF_DD, O_W1L = O_W1H + SZ_BF_W1;
constexpr size_t O_W2H = O_W1L + SZ_BF_W1, O_W2L = O_W2H + SZ_BF_W2;
constexpr size_t O_W3H = O_W2L + SZ_BF_W2, O_W3L = O_W3H + SZ_BF_W3;
constexpr size_t O_B1P = O_W3L + SZ_BF_W3, O_B2P = O_B1P + 1024;
constexpr size_t O_QH  = O_B2P + 1024,     O_QL  = O_QH + SZ_BF_MD;
constexpr size_t O_KH  = O_QL + SZ_BF_MD,  O_KL  = O_KH + SZ_BF_MD;
constexpr size_t O_VTH = O_KL + SZ_BF_MD,  O_VTL = O_VTH + SZ_BF_MD;
constexpr size_t O_CCH = O_VTL + SZ_BF_MD, O_CCL = O_CCH + SZ_BF_MD;
constexpr size_t O_Y   = O_CCL + SZ_BF_MD;
constexpr size_t O_YH  = O_Y + SZ_F_MD,    O_YL  = O_YH + SZ_BF_MD;
constexpr size_t O_F1H = O_YL + SZ_BF_MD,  O_F1L = O_F1H + SZ_BF_MF;
constexpr size_t O_F2H = O_F1L + SZ_BF_MF, O_F2L = O_F2H + SZ_BF_MF;
constexpr size_t O_F3  = O_F2L + SZ_BF_MF;
constexpr size_t O_Y2  = O_F3 + SZ_F_MD;
constexpr size_t ARENA = O_Y2 + SZ_F_MD;

__device__ __align__(1024) unsigned char g_arena[ARENA];

// ---------------- helpers -----------------------------------------------------
__device__ __forceinline__ uint32_t su32(const void* p) {
    uint32_t a;
    asm("{ .reg .u64 t; cvta.to.shared.u64 t, %1; cvt.u32.u64 %0, t; }" : "=r"(a) : "l"(p));
    return a;
}
__device__ __forceinline__ void cpa16(uint32_t d, const void* s) {
    asm volatile("cp.async.ca.shared.global [%0], [%1], 16;" :: "r"(d), "l"(s));
}
__device__ __forceinline__ void cp_commit() {
    asm volatile("cp.async.commit_group;" ::: "memory");
}
__device__ __forceinline__ void ldm4(uint32_t* r, uint32_t a) {
    asm volatile("ldmatrix.sync.aligned.m8n8.x4.shared.b16 {%0,%1,%2,%3}, [%4];"
        : "=r"(r[0]), "=r"(r[1]), "=r"(r[2]), "=r"(r[3]) : "r"(a));
}
__device__ __forceinline__ void mma16816(float* c, const uint32_t* a, uint32_t b0, uint32_t b1) {
    asm volatile("mma.sync.aligned.m16n8k16.row.col.f32.bf16.bf16.f32 "
        "{%0,%1,%2,%3}, {%4,%5,%6,%7}, {%8,%9}, {%0,%1,%2,%3};"
        : "+f"(c[0]), "+f"(c[1]), "+f"(c[2]), "+f"(c[3])
        : "r"(a[0]), "r"(a[1]), "r"(a[2]), "r"(a[3]), "r"(b0), "r"(b1));
}
__device__ __forceinline__ void split2(float v, __nv_bfloat16& h, __nv_bfloat16& l) {
    h = __float2bfloat16(v);
    l = __float2bfloat16(v - __bfloat162float(h));
}
__device__ __forceinline__ uint32_t pack2(__nv_bfloat16 a, __nv_bfloat16 b) {
    return (uint32_t)__bfloat16_as_ushort(a) | ((uint32_t)__bfloat16_as_ushort(b) << 16);
}

// ---------------- bf16 HMMA GEMM (unchanged from passing R7 kernel) ------------
template<int BN, int MODE, bool RELU>
__global__ __launch_bounds__(512, 1)
void gemm_mma(const __nv_bfloat16* __restrict__ Ah, const __nv_bfloat16* __restrict__ Al,
              const __nv_bfloat16* __restrict__ Bh, const __nv_bfloat16* __restrict__ Bl,
              const float* __restrict__ bias, const float* __restrict__ Res,
              float* __restrict__ Cf, __nv_bfloat16* __restrict__ Chi, __nv_bfloat16* __restrict__ Clo,
              int K, int lda, int ldb, int ldc,
              long sA, long sA2, long sB, long sB2, long sC, long sC2,
              int zdiv, float alpha)
{
    constexpr int WGN = BN / 32;
    constexpr int WGM = 16 / WGN;
    constexpr int WTM = 128 / WGM;
    constexpr int MT  = WTM / 16;
    constexpr int LDS = 40;
    constexpr int A_H = 128 * LDS;
    constexpr int B_H = BN * LDS;
    constexpr int STG = 2 * A_H + 2 * B_H;

    extern __shared__ __align__(16) __nv_bfloat16 sm[];
    const uint32_t sb = su32(sm);

    const int tid = threadIdx.x, wid = tid >> 5, lane = tid & 31;
    const int wn = wid % WGN, wm = wid / WGN;

    const int bz = blockIdx.z;
    const long zo1 = bz / zdiv, zo2 = bz % zdiv;
    Ah += zo1 * sA + zo2 * sA2;  Al += zo1 * sA + zo2 * sA2;
    Bh += zo1 * sB + zo2 * sB2;  Bl += zo1 * sB + zo2 * sB2;
    const long coff = zo1 * sC + zo2 * sC2;

    const int mBlk = blockIdx.y * 128, nBlk = blockIdx.x * BN;
    Ah += (long)mBlk * lda; Al += (long)mBlk * lda;
    Bh += (long)nBlk * ldb; Bl += (long)nBlk * ldb;

    auto stage_copy = [&](int t, int s) {
        const int kt = t * 32;
        const uint32_t st = sb + 2u * (uint32_t)(s * STG);
        for (int i = tid; i < 128 * 4; i += 512) {
            const int r = i >> 2, cg = (i & 3) * 8;
            const long go = (long)r * lda + kt + cg;
            const uint32_t d = st + 2u * (uint32_t)(r * LDS + cg);
            cpa16(d,             Ah + go);
            cpa16(d + 2u * A_H,  Al + go);
        }
        for (int i = tid; i < BN * 4; i += 512) {
            const int r = i >> 2, cg = (i & 3) * 8;
            const long go = (long)r * ldb + kt + cg;
            const uint32_t d = st + 2u * (uint32_t)(2 * A_H + r * LDS + cg);
            cpa16(d,             Bh + go);
            cpa16(d + 2u * B_H,  Bl + go);
        }
        cp_commit();
    };

    float acc[MT][4][4];
    #pragma unroll
    for (int i = 0; i < MT; i++)
        #pragma unroll
        for (int j = 0; j < 4; j++)
            #pragma unroll
            for (int q = 0; q < 4; q++) acc[i][j][q] = 0.f;

    const int nt = K / 32;
    stage_copy(0, 0);

    for (int t = 0; t < nt; t++) {
        if (t + 1 < nt) stage_copy(t + 1, (t + 1) & 1);
        if (t + 1 < nt) asm volatile("cp.async.wait_group 1;" ::: "memory");
        else            asm volatile("cp.async.wait_group 0;" ::: "memory");
        __syncthreads();

        const int s = t & 1;
        const uint32_t ab = sb + 2u * (uint32_t)(s * STG);
        const uint32_t bb = ab + 2u * (uint32_t)(2 * A_H);
        const int arow = wm * WTM + (lane & 15);
        const int bmat = lane >> 3, bmr = lane & 7;

        #pragma unroll
        for (int ks = 0; ks < 2; ks++) {
            const int acol = ks * 16 + (lane >> 4) * 8;
            uint32_t afh[MT][4], afl[MT][4];
            #pragma unroll
            for (int mt = 0; mt < MT; mt++) {
                const uint32_t ad = ab + 2u * (uint32_t)((arow + mt * 16) * LDS + acol);
                ldm4(afh[mt], ad);
                ldm4(afl[mt], ad + 2u * A_H);
            }
            uint32_t bfh[8], bfl[8];
            #pragma unroll
            for (int p = 0; p < 2; p++) {
                const int n = wn * 32 + (p * 2 + (bmat >> 1)) * 8 + bmr;
                const int koff = ks * 16 + (bmat & 1) * 8;
                const uint32_t bd = bb + 2u * (uint32_t)(n * LDS + koff);
                ldm4(&bfh[p * 4], bd);
                ldm4(&bfl[p * 4], bd + 2u * B_H);
            }
            #pragma unroll
            for (int mt = 0; mt < MT; mt++) {
                #pragma unroll
                for (int n4 = 0; n4 < 4; n4++) {
                    const int bi = (n4 >> 1) * 4 + (n4 & 1) * 2;
                    mma16816(acc[mt][n4], afh[mt], bfh[bi], bfh[bi + 1]);
                    mma16816(acc[mt][n4], afh[mt], bfl[bi], bfl[bi + 1]);
                    mma16816(acc[mt][n4], afl[mt], bfh[bi], bfh[bi + 1]);
                }
            }
        }
        __syncthreads();
    }

    const int mBase = mBlk + wm * WTM + (lane >> 2);
    const int nBase = nBlk + wn * 32 + (lane & 3) * 2;
    #pragma unroll
    for (int mt = 0; mt < MT; mt++) {
        #pragma unroll
        for (int n4 = 0; n4 < 4; n4++) {
            const int n0 = nBase + n4 * 8;
            float bx = 0.f, by = 0.f;
            if (bias) { bx = bias[n0]; by = bias[n0 + 1]; }
            #pragma unroll
            for (int half = 0; half < 2; half++) {
                const int m = mBase + mt * 16 + half * 8;
                float v0 = acc[mt][n4][half * 2 + 0] + bx;
                float v1 = acc[mt][n4][half * 2 + 1] + by;
                v0 *= alpha; v1 *= alpha;
                if (RELU) { v0 = fmaxf(v0, 0.f); v1 = fmaxf(v1, 0.f); }
                if (MODE == 0) {
                    const long ro = coff + (long)m * ldc + n0;
                    if (Res) { v0 += Res[ro]; v1 += Res[ro + 1]; }
                    *reinterpret_cast<float2*>(Cf + ro) = make_float2(v0, v1);
                } else if (MODE == 1) {
                    const long ro = coff + (long)m * ldc + n0;
                    __nv_bfloat16 h0, h1, l0, l1;
                    split2(v0, h0, l0); split2(v1, h1, l1);
                    *reinterpret_cast<uint32_t*>(Chi + ro) = pack2(h0, h1);
                    *reinterpret_cast<uint32_t*>(Clo + ro) = pack2(l0, l1);
                } else {
                    const int bq = m >> 9, tq = m & 511;
                    __nv_bfloat16 h0, h1, l0, l1;
                    split2(v0, h0, l0); split2(v1, h1, l1);
                    const long a0 = ((long)(bq * 512 + n0)) * 512 + tq;
                    const long a1 = a0 + 512;
                    Chi[a0] = h0; Clo[a0] = l0;
                    Chi[a1] = h1; Clo[a1] = l1;
                }
            }
        }
    }
}

// ---------------- fused flash attention ----------------------------------------
// Per CTA: (q-tile of 128 rows) x (one b,h). Q,K [128,64] pairs; V^T [64,128]
// pairs; online softmax; P routed through smem; output concat pairs.
__global__ __launch_bounds__(512, 1)
void flash_attn(const __nv_bfloat16* __restrict__ Qh, const __nv_bfloat16* __restrict__ Ql,
                const __nv_bfloat16* __restrict__ Kh, const __nv_bfloat16* __restrict__ Kl,
                const __nv_bfloat16* __restrict__ Vh, const __nv_bfloat16* __restrict__ Vl,
                __nv_bfloat16* __restrict__ Ch, __nv_bfloat16* __restrict__ Cl)
{
    // smem byte offsets
    constexpr int oQH = 0,      oQL = 18432;     // [128][72] halves each
    constexpr int oKH = 36864,  oKL = 55296;     // [128][72]
    constexpr int oVH = 73728,  oVL = 91136;     // [64][136]
    constexpr int oPH = 108544, oPL = 143360;    // [128][136]
    constexpr int oPM = 178176, oPS = 180224;    // float [128][4] each
    constexpr int oM  = 182272, oL = 182784, oS = 183296;  // float [128] each
    extern __shared__ __align__(16) char smf[];
    const uint32_t sb = su32(smf);
    float* pm   = reinterpret_cast<float*>(smf + oPM);
    float* ps   = reinterpret_cast<float*>(smf + oPS);
    float* mrow = reinterpret_cast<float*>(smf + oM);
    float* lrow = reinterpret_cast<float*>(smf + oL);
    float* srow = reinterpret_cast<float*>(smf + oS);

    const int tid = threadIdx.x, wid = tid >> 5, lane = tid & 31;
    const int wm = wid >> 2, wn = wid & 3;   // GEMM1: 4x4 warps, 32x32 tiles
    const int om = wid >> 1, on = wid & 1;   // GEMM2: 8x2 warps, 16x32 tiles
    const int qt = blockIdx.x, z = blockIdx.y;
    const int b = z >> 3, h = z & 7;
    const int bmat = lane >> 3, bmr = lane & 7;

    // load Q tile [128][64] hi/lo
    {
        const long base = (long)(b * 512 + qt * 128) * 512 + h * 64;
        for (int i = tid; i < 1024; i += 512) {
            const int r = i >> 3, c8 = (i & 7) * 8;
            const long go = base + (long)r * 512 + c8;
            *reinterpret_cast<uint4*>(smf + oQH + 2 * (r * 72 + c8)) =
                *reinterpret_cast<const uint4*>(Qh + go);
            *reinterpret_cast<uint4*>(smf + oQL + 2 * (r * 72 + c8)) =
                *reinterpret_cast<const uint4*>(Ql + go);
        }
    }
    if (tid < 128) { mrow[tid] = -1e30f; lrow[tid] = 0.f; }

    float acc_o[4][4];
    #pragma unroll
    for (int i = 0; i < 4; i++)
        #pragma unroll
        for (int j = 0; j < 4; j++) acc_o[i][j] = 0.f;

    __syncthreads();

    for (int kb = 0; kb < 4; kb++) {
        // ---- load K block [128][64], V^T block [64][128] ----
        {
            const long kbase = (long)(b * 512 + kb * 128) * 512 + h * 64;
            for (int i = tid; i < 1024; i += 512) {
                const int r = i >> 3, c8 = (i & 7) * 8;
                const long go = kbase + (long)r * 512 + c8;
                *reinterpret_cast<uint4*>(smf + oKH + 2 * (r * 72 + c8)) =
                    *reinterpret_cast<const uint4*>(Kh + go);
                *reinterpret_cast<uint4*>(smf + oKL + 2 * (r * 72 + c8)) =
                    *reinterpret_cast<const uint4*>(Kl + go);
            }
            const long vbase = (long)(b * 512 + h * 64) * 512 + kb * 128;
            for (int i = tid; i < 1024; i += 512) {
                const int r = i >> 4, c8 = (i & 15) * 8;
                const long go = vbase + (long)r * 512 + c8;
                *reinterpret_cast<uint4*>(smf + oVH + 2 * (r * 136 + c8)) =
                    *reinterpret_cast<const uint4*>(Vh + go);
                *reinterpret_cast<uint4*>(smf + oVL + 2 * (r * 136 + c8)) =
                    *reinterpret_cast<const uint4*>(Vl + go);
            }
        }
        __syncthreads();

        // ---- GEMM1: scores[128,128] = Q @ K^T (3-product emu) ----
        float acc_s[2][4][4];
        #pragma unroll
        for (int i = 0; i < 2; i++)
            #pragma unroll
            for (int j = 0; j < 4; j++)
                #pragma unroll
                for (int q = 0; q < 4; q++) acc_s[i][j][q] = 0.f;

        #pragma unroll
        for (int ks = 0; ks < 4; ks++) {
            const int acol = ks * 16 + (lane >> 4) * 8;
            uint32_t afh[2][4], afl[2][4];
            #pragma unroll
            for (int mt = 0; mt < 2; mt++) {
                const uint32_t ad = sb + oQH +
                    2u * (uint32_t)((wm * 32 + mt * 16 + (lane & 15)) * 72 + acol);
                ldm4(afh[mt], ad);
                ldm4(afl[mt], ad + (oQL - oQH));
            }
            uint32_t bfh[8], bfl[8];
            #pragma unroll
            for (int p = 0; p < 2; p++) {
                const int n = wn * 32 + (p * 2 + (bmat >> 1)) * 8 + bmr;
                const int koff = ks * 16 + (bmat & 1) * 8;
                const uint32_t bd = sb + oKH + 2u * (uint32_t)(n * 72 + koff);
                ldm4(&bfh[p * 4], bd);
                ldm4(&bfl[p * 4], bd + (oKL - oKH));
            }
            #pragma unroll
            for (int mt = 0; mt < 2; mt++) {
                #pragma unroll
                for (int n4 = 0; n4 < 4; n4++) {
                    const int bi = (n4 >> 1) * 4 + (n4 & 1) * 2;
                    mma16816(acc_s[mt][n4], afh[mt], bfh[bi], bfh[bi + 1]);
                    mma16816(acc_s[mt][n4], afh[mt], bfl[bi], bfl[bi + 1]);
                    mma16816(acc_s[mt][n4], afl[mt], bfh[bi], bfh[bi + 1]);
                }
            }
        }

        // ---- row max partials ----
        #pragma unroll
        for (int mt = 0; mt < 2; mt++) {
            #pragma unroll
            for (int half = 0; half < 2; half++) {
                float vmax = -1e30f;
                #pragma unroll
                for (int n4 = 0; n4 < 4; n4++)
                    vmax = fmaxf(vmax, fmaxf(acc_s[mt][n4][half * 2], acc_s[mt][n4][half * 2 + 1]));
                vmax = fmaxf(vmax, __shfl_xor_sync(0xffffffffu, vmax, 1));
                vmax = fmaxf(vmax, __shfl_xor_sync(0xffffffffu, vmax, 2));
                if ((lane & 3) == 0) {
                    const int row = wm * 32 + mt * 16 + half * 8 + (lane >> 2);
                    pm[row * 4 + wn] = vmax;
                }
            }
        }
        __syncthreads();
        if (tid < 128) {
            const float mb = fmaxf(fmaxf(pm[tid * 4], pm[tid * 4 + 1]),
                                   fmaxf(pm[tid * 4 + 2], pm[tid * 4 + 3]));
            const float mn = fmaxf(mrow[tid], mb);
            srow[tid] = __expf(mrow[tid] - mn);
            mrow[tid] = mn;
        }
        __syncthreads();

        // ---- P = exp(s - m), row-sum partials, store hi/lo to smem ----
        #pragma unroll
        for (int mt = 0; mt < 2; mt++) {
            #pragma unroll
            for (int half = 0; half < 2; half++) {
                const int row = wm * 32 + mt * 16 + half * 8 + (lane >> 2);
                const float mi = mrow[row];
                float rs = 0.f;
                #pragma unroll
                for (int n4 = 0; n4 < 4; n4++) {
                    const float p0 = __expf(acc_s[mt][n4][half * 2 + 0] - mi);
                    const float p1 = __expf(acc_s[mt][n4][half * 2 + 1] - mi);
                    rs += p0 + p1;
                    const int col = wn * 32 + n4 * 8 + (lane & 3) * 2;
                    __nv_bfloat16 h0, h1, l0, l1;
                    split2(p0, h0, l0); split2(p1, h1, l1);
                    *reinterpret_cast<uint32_t*>(smf + oPH + 2 * (row * 136 + col)) = pack2(h0, h1);
                    *reinterpret_cast<uint32_t*>(smf + oPL + 2 * (row * 136 + col)) = pack2(l0, l1);
                }
                rs += __shfl_xor_sync(0xffffffffu, rs, 1);
                rs += __shfl_xor_sync(0xffffffffu, rs, 2);
                if ((lane & 3) == 0) ps[row * 4 + wn] = rs;
            }
        }
        __syncthreads();

        if (tid < 128)
            lrow[tid] = lrow[tid] * srow[tid] +
                        (ps[tid * 4] + ps[tid * 4 + 1] + ps[tid * 4 + 2] + ps[tid * 4 + 3]);

        // ---- rescale acc_o ----
        {
            const int r0 = om * 16 + (lane >> 2);
            const float s0 = srow[r0], s1 = srow[r0 + 8];
            #pragma unroll
            for (int n4 = 0; n4 < 4; n4++) {
                acc_o[n4][0] *= s0; acc_o[n4][1] *= s0;
                acc_o[n4][2] *= s1; acc_o[n4][3] *= s1;
            }
        }

        // ---- GEMM2: acc_o += P @ V^T (3-product emu) ----
        #pragma unroll
        for (int ks2 = 0; ks2 < 8; ks2++) {
            const int acol = ks2 * 16 + (lane >> 4) * 8;
            uint32_t pah[4], pal[4];
            {
                const uint32_t ad = sb + oPH +
                    2u * (uint32_t)((om * 16 + (lane & 15)) * 136 + acol);
                ldm4(pah, ad);
                ldm4(pal, ad + (oPL - oPH));
            }
            uint32_t bfh[8], bfl[8];
            #pragma unroll
            for (int p = 0; p < 2; p++) {
                const int n = on * 32 + (p * 2 + (bmat >> 1)) * 8 + bmr;
                const int koff = ks2 * 16 + (bmat & 1) * 8;
                const uint32_t bd = sb + oVH + 2u * (uint32_t)(n * 136 + koff);
                ldm4(&bfh[p * 4], bd);
                ldm4(&bfl[p * 4], bd + (oVL - oVH));
            }
            #pragma unroll
            for (int n4 = 0; n4 < 4; n4++) {
                const int bi = (n4 >> 1) * 4 + (n4 & 1) * 2;
                mma16816(acc_o[n4], pah, bfh[bi], bfh[bi + 1]);
                mma16816(acc_o[n4], pah, bfl[bi], bfl[bi + 1]);
                mma16816(acc_o[n4], pal, bfh[bi], bfh[bi + 1]);
            }
        }
        __syncthreads();
    }

    // ---- epilogue: divide by l, write concat pairs ----
    if (tid < 128) srow[tid] = 1.f / lrow[tid];
    __syncthreads();
    {
        const int r0 = om * 16 + (lane >> 2);
        const float i0 = srow[r0], i1 = srow[r0 + 8];
        const long gq = (long)(b * 512 + qt * 128);
        #pragma unroll
        for (int n4 = 0; n4 < 4; n4++) {
            const int c0 = on * 32 + n4 * 8 + (lane & 3) * 2;
            const float v00 = acc_o[n4][0] * i0, v01 = acc_o[n4][1] * i0;
            const float v10 = acc_o[n4][2] * i1, v11 = acc_o[n4][3] * i1;
            const long a0 = (gq + r0) * 512 + h * 64 + c0;
            const long a1 = (gq + r0 + 8) * 512 + h * 64 + c0;
            __nv_bfloat16 h0, h1, l0, l1;
            split2(v00, h0, l0); split2(v01, h1, l1);
            *reinterpret_cast<uint32_t*>(Ch + a0) = pack2(h0, h1);
            *reinterpret_cast<uint32_t*>(Cl + a0) = pack2(l0, l1);
            split2(v10, h0, l0); split2(v11, h1, l1);
            *reinterpret_cast<uint32_t*>(Ch + a1) = pack2(h0, h1);
            *reinterpret_cast<uint32_t*>(Cl + a1) = pack2(l0, l1);
        }
    }
}

// ---------------- fp32 -> bf16 hi/lo split with zero-padding -------------------
__global__ void split_kernel(const float* __restrict__ src, __nv_bfloat16* __restrict__ hi,
                             __nv_bfloat16* __restrict__ lo, int rs, int cs, int rd, int cd)
{
    const long idx4 = ((long)blockIdx.x * blockDim.x + threadIdx.x) * 4;
    if (idx4 >= (long)rd * cd) return;
    const int r = (int)(idx4 / cd), c = (int)(idx4 % cd);
    float4 v = make_float4(0.f, 0.f, 0.f, 0.f);
    if (r < rs && c < cs) v = *reinterpret_cast<const float4*>(src + (long)r * cs + c);
    __nv_bfloat16 h0, h1, h2, h3, l0, l1, l2, l3;
    split2(v.x, h0, l0); split2(v.y, h1, l1); split2(v.z, h2, l2); split2(v.w, h3, l3);
    *reinterpret_cast<uint2*>(hi + idx4) = make_uint2(pack2(h0, h1), pack2(h2, h3));
    *reinterpret_cast<uint2*>(lo + idx4) = make_uint2(pack2(l0, l1), pack2(l2, l3));
}

__global__ void pad_bias(const float* __restrict__ s, float* __restrict__ d, int n) {
    const int i = threadIdx.x;
    d[i] = (i < n) ? s[i] : 0.f;
}

// ---------------- 2-D LayerNorm over (S,D) per batch ---------------------------
template<bool PAIR>
__global__ __launch_bounds__(1024)
void layernorm_kernel(const float* __restrict__ X, const float* __restrict__ Add,
                      const float* __restrict__ gamma, const float* __restrict__ beta,
                      float* __restrict__ out, __nv_bfloat16* __restrict__ oh,
                      __nv_bfloat16* __restrict__ ol)
{
    const long base = (long)blockIdx.x * LN_N;
    float s1 = 0.f, s2 = 0.f;
    for (int i = threadIdx.x * 4; i < LN_N; i += 4096) {
        float4 v = *reinterpret_cast<const float4*>(X + base + i);
        if (Add) {
            float4 a = *reinterpret_cast<const float4*>(Add + base + i);
            v.x += a.x; v.y += a.y; v.z += a.z; v.w += a.w;
        }
        s1 += (v.x + v.y) + (v.z + v.w);
        s2 += (v.x*v.x + v.y*v.y) + (v.z*v.z + v.w*v.w);
    }
    __shared__ float r1[32], r2[32];
    const int lane = threadIdx.x & 31, wid = threadIdx.x >> 5;
    #pragma unroll
    for (int o = 16; o; o >>= 1) {
        s1 += __shfl_xor_sync(0xffffffffu, s1, o);
        s2 += __shfl_xor_sync(0xffffffffu, s2, o);
    }
    if (!lane) { r1[wid] = s1; r2[wid] = s2; }
    __syncthreads();
    if (threadIdx.x < 32) {
        s1 = r1[threadIdx.x]; s2 = r2[threadIdx.x];
        #pragma unroll
        for (int o = 16; o; o >>= 1) {
            s1 += __shfl_xor_sync(0xffffffffu, s1, o);
            s2 += __shfl_xor_sync(0xffffffffu, s2, o);
        }
        if (!threadIdx.x) { r1[0] = s1; r2[0] = s2; }
    }
    __syncthreads();
    const float mean = r1[0] / (float)LN_N;
    const float var  = r2[0] / (float)LN_N - mean * mean;
    const float rstd = rsqrtf(var + 1e-5f);

    for (int i = threadIdx.x * 4; i < LN_N; i += 4096) {
        float4 v = *reinterpret_cast<const float4*>(X + base + i);
        if (Add) {
            float4 a = *reinterpret_cast<const float4*>(Add + base + i);
            v.x += a.x; v.y += a.y; v.z += a.z; v.w += a.w;
        }
        float4 g  = *reinterpret_cast<const float4*>(gamma + i);
        float4 bt = *reinterpret_cast<const float4*>(beta  + i);
        float4 o;
        o.x = (v.x - mean) * rstd * g.x + bt.x;
        o.y = (v.y - mean) * rstd * g.y + bt.y;
        o.z = (v.z - mean) * rstd * g.z + bt.z;
        o.w = (v.w - mean) * rstd * g.w + bt.w;
        *reinterpret_cast<float4*>(out + base + i) = o;
        if (PAIR) {
            __nv_bfloat16 h0, h1, h2, h3, l0, l1, l2, l3;
            split2(o.x, h0, l0); split2(o.y, h1, l1); split2(o.z, h2, l2); split2(o.w, h3, l3);
            *reinterpret_cast<uint2*>(oh + base + i) = make_uint2(pack2(h0, h1), pack2(h2, h3));
            *reinterpret_cast<uint2*>(ol + base + i) = make_uint2(pack2(l0, l1), pack2(l2, l3));
        }
    }
}

// ---------------- launch --------------------------------------------------------
extern "C" void kernel_launch(void* const* d_in, const int* in_sizes, int n_in,
                              void* d_out, int out_size)
{
    const float* x  = (const float*)d_in[0];
    const float* Wq = (const float*)d_in[1];
    const float* bq = (const float*)d_in[2];
    const float* Wk = (const float*)d_in[3];
    const float* bk = (const float*)d_in[4];
    const float* Wv = (const float*)d_in[5];
    const float* bv = (const float*)d_in[6];
    const float* Wo = (const float*)d_in[7];
    const float* bo = (const float*)d_in[8];
    const float* W1 = (const float*)d_in[9];
    const float* b1 = (const float*)d_in[10];
    const float* W2 = (const float*)d_in[11];
    const float* b2 = (const float*)d_in[12];
    const float* W3 = (const float*)d_in[13];
    const float* b3 = (const float*)d_in[14];
    const float* gamma = (const float*)d_in[15];
    const float* beta  = (const float*)d_in[16];
    float* out = (float*)d_out;

    unsigned char* ar;
    cudaGetSymbolAddress((void**)&ar, g_arena);
    #define BF(o) reinterpret_cast<__nv_bfloat16*>(ar + (o))
    #define FP(o) reinterpret_cast<float*>(ar + (o))

    const int SM128 = 2 * (2 * 128 * 40 + 2 * 128 * 40) * 2;   // 81920
    const int SMFL  = 183808;
    cudaFuncSetAttribute((const void*)gemm_mma<128, 0, false>, cudaFuncAttributeMaxDynamicSharedMemorySize, SM128);
    cudaFuncSetAttribute((const void*)gemm_mma<128, 1, false>, cudaFuncAttributeMaxDynamicSharedMemorySize, SM128);
    cudaFuncSetAttribute((const void*)gemm_mma<128, 1, true >, cudaFuncAttributeMaxDynamicSharedMemorySize, SM128);
    cudaFuncSetAttribute((const void*)gemm_mma<128, 2, false>, cudaFuncAttributeMaxDynamicSharedMemorySize, SM128);
    cudaFuncSetAttribute((const void*)flash_attn, cudaFuncAttributeMaxDynamicSharedMemorySize, SMFL);

    // ---- splits (fp32 -> bf16 hi/lo, with padding) ----
    auto g4 = [](long n) { return (unsigned)((n / 4 + 255) / 256); };
    split_kernel<<<g4((long)NM*ND),   256>>>(x,  BF(O_XH),  BF(O_XL),  NM, ND, NM, ND);
    split_kernel<<<g4((long)ND*ND),   256>>>(Wq, BF(O_WQH), BF(O_WQL), ND, ND, ND, ND);
    split_kernel<<<g4((long)ND*ND),   256>>>(Wk, BF(O_WKH), BF(O_WKL), ND, ND, ND, ND);
    split_kernel<<<g4((long)ND*ND),   256>>>(Wv, BF(O_WVH), BF(O_WVL), ND, ND, ND, ND);
    split_kernel<<<g4((long)ND*ND),   256>>>(Wo, BF(O_WOH), BF(O_WOL), ND, ND, ND, ND);
    split_kernel<<<g4((long)NFP*ND),  256>>>(W1, BF(O_W1H), BF(O_W1L), NFF, ND,  NFP, ND);
    split_kernel<<<g4((long)NFP*NFP), 256>>>(W2, BF(O_W2H), BF(O_W2L), NFF, NFF, NFP, NFP);
    split_kernel<<<g4((long)ND*NFP),  256>>>(W3, BF(O_W3H), BF(O_W3L), ND,  NFF, ND,  NFP);
    pad_bias<<<1, 256>>>(b1, FP(O_B1P), NFF);
    pad_bias<<<1, 256>>>(b2, FP(O_B2P), NFF);

    // ---- 1) Q/K/V projections (q pre-scaled by 1/8; v written transposed) ----
    {
        dim3 grid(4, 128, 1);
        gemm_mma<128, 1, false><<<grid, 512, SM128>>>(
            BF(O_XH), BF(O_XL), BF(O_WQH), BF(O_WQL), bq, nullptr,
            nullptr, BF(O_QH), BF(O_QL), ND, ND, ND, ND,
            0, 0, 0, 0, 0, 0, 1, 0.125f);
        gemm_mma<128, 1, false><<<grid, 512, SM128>>>(
            BF(O_XH), BF(O_XL), BF(O_WKH), BF(O_WKL), bk, nullptr,
            nullptr, BF(O_KH), BF(O_KL), ND, ND, ND, ND,
            0, 0, 0, 0, 0, 0, 1, 1.f);
        gemm_mma<128, 2, false><<<grid, 512, SM128>>>(
            BF(O_XH), BF(O_XL), BF(O_WVH), BF(O_WVL), bv, nullptr,
            nullptr, BF(O_VTH), BF(O_VTL), ND, ND, ND, ND,
            0, 0, 0, 0, 0, 0, 1, 1.f);
    }

    // ---- 2-4) fused flash attention -> concat pairs ----
    {
        dim3 grid(4, NB * NH);
        flash_attn<<<grid, 512, SMFL>>>(
            BF(O_QH), BF(O_QL), BF(O_KH), BF(O_KL),
            BF(O_VTH), BF(O_VTL), BF(O_CCH), BF(O_CCL));
    }

    // ---- 5) y = concat @ Wo^T + bo + x  (fp32) ----
    {
        dim3 grid(4, 128, 1);
        gemm_mma<128, 0, false><<<grid, 512, SM128>>>(
            BF(O_CCH), BF(O_CCL), BF(O_WOH), BF(O_WOL), bo, x,
            FP(O_Y), nullptr, nullptr, ND, ND, ND, ND,
            0, 0, 0, 0, 0, 0, 1, 1.f);
    }

    // ---- 6) y = LN(y), also emit bf16 pair ----
    layernorm_kernel<true><<<NB, 1024>>>(FP(O_Y), nullptr, gamma, beta,
                                         FP(O_Y), BF(O_YH), BF(O_YL));

    // ---- 7) f1 = relu(y @ W1p^T + b1p) pair, N=256 ----
    {
        dim3 grid(2, 128, 1);
        gemm_mma<128, 1, true><<<grid, 512, SM128>>>(
            BF(O_YH), BF(O_YL), BF(O_W1H), BF(O_W1L), FP(O_B1P), nullptr,
            nullptr, BF(O_F1H), BF(O_F1L), ND, ND, ND, NFP,
            0, 0, 0, 0, 0, 0, 1, 1.f);
    }
    // ---- 8) f2 = relu(f1 @ W2p^T + b2p) pair, K=N=256 ----
    {
        dim3 grid(2, 128, 1);
        gemm_mma<128, 1, true><<<grid, 512, SM128>>>(
            BF(O_F1H), BF(O_F1L), BF(O_W2H), BF(O_W2L), FP(O_B2P), nullptr,
            nullptr, BF(O_F2H), BF(O_F2L), NFP, NFP, NFP, NFP,
            0, 0, 0, 0, 0, 0, 1, 1.f);
    }
    // ---- 9) f3 = f2 @ W3p^T + b3 + y  (fp32, residual folded) ----
    {
        dim3 grid(4, 128, 1);
        gemm_mma<128, 0, false><<<grid, 512, SM128>>>(
            BF(O_F2H), BF(O_F2L), BF(O_W3H), BF(O_W3L), b3, FP(O_Y),
            FP(O_F3), nullptr, nullptr, NFP, NFP, NFP, ND,
            0, 0, 0, 0, 0, 0, 1, 1.f);
    }

    // ---- 10) y2 = LN(f3)  (f3 already includes +y) ----
    layernorm_kernel<false><<<NB, 1024>>>(FP(O_F3), nullptr, gamma, beta,
                                          FP(O_Y2), nullptr, nullptr);
    // ---- 11) out = LN(y2) ----
    layernorm_kernel<false><<<NB, 1024>>>(FP(O_Y2), nullptr, gamma, beta,
                                          out, nullptr, nullptr);
}

// round 10
// speedup vs baseline: 2.5567x; 1.1286x over previous
#include <cuda_runtime.h>
#include <cuda_bf16.h>
#include <cstdint>

// ---------------- problem dims ------------------------------------------------
#define NB   32
#define NS   512
#define ND   512
#define NH   8
#define NDK  64
#define NFF  200
#define NFP  256            // padded FF width
#define NM   (NB * NS)      // 16384 rows
#define LN_N (NS * ND)      // 262144 elems per batch for 2-D LayerNorm

// ---------------- arena (single static device allocation) ---------------------
constexpr size_t SZ_BF_MD = (size_t)NM * ND * 2;        // [16384,512] bf16
constexpr size_t SZ_BF_DD = (size_t)ND * ND * 2;        // [512,512]  bf16
constexpr size_t SZ_BF_W1 = (size_t)NFP * ND * 2;
constexpr size_t SZ_BF_W2 = (size_t)NFP * NFP * 2;
constexpr size_t SZ_BF_W3 = (size_t)ND * NFP * 2;
constexpr size_t SZ_F_MD  = (size_t)NM * ND * 4;
constexpr size_t SZ_BF_MF = (size_t)NM * NFP * 2;

constexpr size_t O_XH = 0,                 O_XL = O_XH + SZ_BF_MD;
constexpr size_t O_WQH = O_XL + SZ_BF_MD,  O_WQL = O_WQH + SZ_BF_DD;
constexpr size_t O_WKH = O_WQL + SZ_BF_DD, O_WKL = O_WKH + SZ_BF_DD;
constexpr size_t O_WVH = O_WKL + SZ_BF_DD, O_WVL = O_WVH + SZ_BF_DD;
constexpr size_t O_WOH = O_WVL + SZ_BF_DD, O_WOL = O_WOH + SZ_BF_DD;
constexpr size_t O_W1H = O_WOL + SZ_BF_DD, O_W1L = O_W1H + SZ_BF_W1;
constexpr size_t O_W2H = O_W1L + SZ_BF_W1, O_W2L = O_W2H + SZ_BF_W2;
constexpr size_t O_W3H = O_W2L + SZ_BF_W2, O_W3L = O_W3H + SZ_BF_W3;
constexpr size_t O_B1P = O_W3L + SZ_BF_W3, O_B2P = O_B1P + 1024;
constexpr size_t O_QH  = O_B2P + 1024,     O_QL  = O_QH + SZ_BF_MD;
constexpr size_t O_KH  = O_QL + SZ_BF_MD,  O_KL  = O_KH + SZ_BF_MD;
constexpr size_t O_VTH = O_KL + SZ_BF_MD,  O_VTL = O_VTH + SZ_BF_MD;
constexpr size_t O_CCH = O_VTL + SZ_BF_MD, O_CCL = O_CCH + SZ_BF_MD;
constexpr size_t O_Y   = O_CCL + SZ_BF_MD;
constexpr size_t O_YH  = O_Y + SZ_F_MD,    O_YL  = O_YH + SZ_BF_MD;
constexpr size_t O_F1H = O_YL + SZ_BF_MD,  O_F1L = O_F1H + SZ_BF_MF;
constexpr size_t O_F2H = O_F1L + SZ_BF_MF, O_F2L = O_F2H + SZ_BF_MF;
constexpr size_t O_F3  = O_F2L + SZ_BF_MF;
constexpr size_t O_Y2  = O_F3 + SZ_F_MD;
constexpr size_t ARENA = O_Y2 + SZ_F_MD;

__device__ __align__(1024) unsigned char g_arena[ARENA];

// ---------------- helpers -----------------------------------------------------
__device__ __forceinline__ uint32_t su32(const void* p) {
    uint32_t a;
    asm("{ .reg .u64 t; cvta.to.shared.u64 t, %1; cvt.u32.u64 %0, t; }" : "=r"(a) : "l"(p));
    return a;
}
__device__ __forceinline__ void cpa16(uint32_t d, const void* s) {
    asm volatile("cp.async.ca.shared.global [%0], [%1], 16;" :: "r"(d), "l"(s));
}
__device__ __forceinline__ void cp_commit() {
    asm volatile("cp.async.commit_group;" ::: "memory");
}
__device__ __forceinline__ void ldm4(uint32_t* r, uint32_t a) {
    asm volatile("ldmatrix.sync.aligned.m8n8.x4.shared.b16 {%0,%1,%2,%3}, [%4];"
        : "=r"(r[0]), "=r"(r[1]), "=r"(r[2]), "=r"(r[3]) : "r"(a));
}
__device__ __forceinline__ void mma16816(float* c, const uint32_t* a, uint32_t b0, uint32_t b1) {
    asm volatile("mma.sync.aligned.m16n8k16.row.col.f32.bf16.bf16.f32 "
        "{%0,%1,%2,%3}, {%4,%5,%6,%7}, {%8,%9}, {%0,%1,%2,%3};"
        : "+f"(c[0]), "+f"(c[1]), "+f"(c[2]), "+f"(c[3])
        : "r"(a[0]), "r"(a[1]), "r"(a[2]), "r"(a[3]), "r"(b0), "r"(b1));
}
__device__ __forceinline__ void split2(float v, __nv_bfloat16& h, __nv_bfloat16& l) {
    h = __float2bfloat16(v);
    l = __float2bfloat16(v - __bfloat162float(h));
}
__device__ __forceinline__ uint32_t pack2(__nv_bfloat16 a, __nv_bfloat16 b) {
    return (uint32_t)__bfloat16_as_ushort(a) | ((uint32_t)__bfloat16_as_ushort(b) << 16);
}

// ---------------- bf16 HMMA GEMM: 128x128 block, 4 warps of 64x64 --------------
// A [M][K] row-major hi/lo, B [N][K] row-major hi/lo; 3-product fp32 emu.
// MODE 0: f32 out (+bias)(+Res)  MODE 1: bf16 pair out (+bias)(RELU)(alpha)
// MODE 2: bf16 pair out in v-transposed layout vt[(b*512+n)*512+t]
template<int MODE, bool RELU>
__global__ __launch_bounds__(128, 2)
void gemm_mma(const __nv_bfloat16* __restrict__ Ah, const __nv_bfloat16* __restrict__ Al,
              const __nv_bfloat16* __restrict__ Bh, const __nv_bfloat16* __restrict__ Bl,
              const float* __restrict__ bias, const float* __restrict__ Res,
              float* __restrict__ Cf, __nv_bfloat16* __restrict__ Chi, __nv_bfloat16* __restrict__ Clo,
              int K, int lda, int ldb, int ldc,
              float alpha)
{
    constexpr int LDS = 40;               // smem row stride (halves), conflict-free pad
    constexpr int A_H = 128 * LDS;        // halves per (hi or lo) A buffer
    constexpr int B_H = 128 * LDS;
    constexpr int STG = 2 * A_H + 2 * B_H;

    extern __shared__ __align__(16) __nv_bfloat16 sm[];
    const uint32_t sb = su32(sm);

    const int tid = threadIdx.x, wid = tid >> 5, lane = tid & 31;
    const int wm = wid >> 1, wn = wid & 1;   // 2x2 warps, 64x64 each
    const int bmat = lane >> 3, bmr = lane & 7;

    const int mBlk = blockIdx.y * 128, nBlk = blockIdx.x * 128;
    Ah += (long)mBlk * lda; Al += (long)mBlk * lda;
    Bh += (long)nBlk * ldb; Bl += (long)nBlk * ldb;

    auto stage_copy = [&](int t, int s) {
        const int kt = t * 32;
        const uint32_t st = sb + 2u * (uint32_t)(s * STG);
        #pragma unroll
        for (int j = 0; j < 4; j++) {
            const int i = tid + j * 128;
            const int r = i >> 2, cg = (i & 3) * 8;
            const long goA = (long)r * lda + kt + cg;
            const uint32_t dA = st + 2u * (uint32_t)(r * LDS + cg);
            cpa16(dA,            Ah + goA);
            cpa16(dA + 2u * A_H, Al + goA);
            const long goB = (long)r * ldb + kt + cg;
            const uint32_t dB = st + 2u * (uint32_t)(2 * A_H + r * LDS + cg);
            cpa16(dB,            Bh + goB);
            cpa16(dB + 2u * B_H, Bl + goB);
        }
        cp_commit();
    };

    float acc[4][8][4];
    #pragma unroll
    for (int i = 0; i < 4; i++)
        #pragma unroll
        for (int j = 0; j < 8; j++)
            #pragma unroll
            for (int q = 0; q < 4; q++) acc[i][j][q] = 0.f;

    const int nt = K / 32;
    stage_copy(0, 0);

    for (int t = 0; t < nt; t++) {
        if (t + 1 < nt) stage_copy(t + 1, (t + 1) & 1);
        if (t + 1 < nt) asm volatile("cp.async.wait_group 1;" ::: "memory");
        else            asm volatile("cp.async.wait_group 0;" ::: "memory");
        __syncthreads();

        const int s = t & 1;
        const uint32_t ab = sb + 2u * (uint32_t)(s * STG);
        const uint32_t bb = ab + 2u * (uint32_t)(2 * A_H);

        #pragma unroll
        for (int ks = 0; ks < 2; ks++) {
            const int acol = ks * 16 + (lane >> 4) * 8;
            uint32_t afh[4][4], afl[4][4];
            #pragma unroll
            for (int mt = 0; mt < 4; mt++) {
                const uint32_t ad = ab + 2u * (uint32_t)((wm * 64 + mt * 16 + (lane & 15)) * LDS + acol);
                ldm4(afh[mt], ad);
                ldm4(afl[mt], ad + 2u * A_H);
            }
            uint32_t bfh[16], bfl[16];
            #pragma unroll
            for (int p = 0; p < 4; p++) {
                const int n = wn * 64 + (p * 2 + (bmat >> 1)) * 8 + bmr;
                const int koff = ks * 16 + (bmat & 1) * 8;
                const uint32_t bd = bb + 2u * (uint32_t)(n * LDS + koff);
                ldm4(&bfh[p * 4], bd);
                ldm4(&bfl[p * 4], bd + 2u * B_H);
            }
            #pragma unroll
            for (int mt = 0; mt < 4; mt++) {
                #pragma unroll
                for (int n4 = 0; n4 < 8; n4++) {
                    const int bi = (n4 >> 1) * 4 + (n4 & 1) * 2;
                    mma16816(acc[mt][n4], afh[mt], bfh[bi], bfh[bi + 1]);
                    mma16816(acc[mt][n4], afh[mt], bfl[bi], bfl[bi + 1]);
                    mma16816(acc[mt][n4], afl[mt], bfh[bi], bfh[bi + 1]);
                }
            }
        }
        __syncthreads();
    }

    // ---- epilogue ----
    const int mW = mBlk + wm * 64;
    const int nW = nBlk + wn * 64;
    #pragma unroll
    for (int mt = 0; mt < 4; mt++) {
        #pragma unroll
        for (int n4 = 0; n4 < 8; n4++) {
            const int n0 = nW + n4 * 8 + (lane & 3) * 2;
            float bx = 0.f, by = 0.f;
            if (bias) { bx = bias[n0]; by = bias[n0 + 1]; }
            #pragma unroll
            for (int half = 0; half < 2; half++) {
                const int m = mW + mt * 16 + half * 8 + (lane >> 2);
                float v0 = acc[mt][n4][half * 2 + 0] + bx;
                float v1 = acc[mt][n4][half * 2 + 1] + by;
                v0 *= alpha; v1 *= alpha;
                if (RELU) { v0 = fmaxf(v0, 0.f); v1 = fmaxf(v1, 0.f); }
                if (MODE == 0) {
                    const long ro = (long)m * ldc + n0;
                    if (Res) { v0 += Res[ro]; v1 += Res[ro + 1]; }
                    *reinterpret_cast<float2*>(Cf + ro) = make_float2(v0, v1);
                } else if (MODE == 1) {
                    const long ro = (long)m * ldc + n0;
                    __nv_bfloat16 h0, h1, l0, l1;
                    split2(v0, h0, l0); split2(v1, h1, l1);
                    *reinterpret_cast<uint32_t*>(Chi + ro) = pack2(h0, h1);
                    *reinterpret_cast<uint32_t*>(Clo + ro) = pack2(l0, l1);
                } else {   // MODE 2: vt[(b*512 + n)*512 + t]
                    const int bq = m >> 9, tq = m & 511;
                    __nv_bfloat16 h0, h1, l0, l1;
                    split2(v0, h0, l0); split2(v1, h1, l1);
                    const long a0 = ((long)(bq * 512 + n0)) * 512 + tq;
                    const long a1 = a0 + 512;
                    Chi[a0] = h0; Clo[a0] = l0;
                    Chi[a1] = h1; Clo[a1] = l1;
                }
            }
        }
    }
}

// ---------------- fused flash attention (unchanged from passing R8) ------------
__global__ __launch_bounds__(512, 1)
void flash_attn(const __nv_bfloat16* __restrict__ Qh, const __nv_bfloat16* __restrict__ Ql,
                const __nv_bfloat16* __restrict__ Kh, const __nv_bfloat16* __restrict__ Kl,
                const __nv_bfloat16* __restrict__ Vh, const __nv_bfloat16* __restrict__ Vl,
                __nv_bfloat16* __restrict__ Ch, __nv_bfloat16* __restrict__ Cl)
{
    constexpr int oQH = 0,      oQL = 18432;
    constexpr int oKH = 36864,  oKL = 55296;
    constexpr int oVH = 73728,  oVL = 91136;
    constexpr int oPH = 108544, oPL = 143360;
    constexpr int oPM = 178176, oPS = 180224;
    constexpr int oM  = 182272, oL = 182784, oS = 183296;
    extern __shared__ __align__(16) char smf[];
    const uint32_t sb = su32(smf);
    float* pm   = reinterpret_cast<float*>(smf + oPM);
    float* ps   = reinterpret_cast<float*>(smf + oPS);
    float* mrow = reinterpret_cast<float*>(smf + oM);
    float* lrow = reinterpret_cast<float*>(smf + oL);
    float* srow = reinterpret_cast<float*>(smf + oS);

    const int tid = threadIdx.x, wid = tid >> 5, lane = tid & 31;
    const int wm = wid >> 2, wn = wid & 3;
    const int om = wid >> 1, on = wid & 1;
    const int qt = blockIdx.x, z = blockIdx.y;
    const int b = z >> 3, h = z & 7;
    const int bmat = lane >> 3, bmr = lane & 7;

    {
        const long base = (long)(b * 512 + qt * 128) * 512 + h * 64;
        for (int i = tid; i < 1024; i += 512) {
            const int r = i >> 3, c8 = (i & 7) * 8;
            const long go = base + (long)r * 512 + c8;
            *reinterpret_cast<uint4*>(smf + oQH + 2 * (r * 72 + c8)) =
                *reinterpret_cast<const uint4*>(Qh + go);
            *reinterpret_cast<uint4*>(smf + oQL + 2 * (r * 72 + c8)) =
                *reinterpret_cast<const uint4*>(Ql + go);
        }
    }
    if (tid < 128) { mrow[tid] = -1e30f; lrow[tid] = 0.f; }

    float acc_o[4][4];
    #pragma unroll
    for (int i = 0; i < 4; i++)
        #pragma unroll
        for (int j = 0; j < 4; j++) acc_o[i][j] = 0.f;

    __syncthreads();

    for (int kb = 0; kb < 4; kb++) {
        {
            const long kbase = (long)(b * 512 + kb * 128) * 512 + h * 64;
            for (int i = tid; i < 1024; i += 512) {
                const int r = i >> 3, c8 = (i & 7) * 8;
                const long go = kbase + (long)r * 512 + c8;
                *reinterpret_cast<uint4*>(smf + oKH + 2 * (r * 72 + c8)) =
                    *reinterpret_cast<const uint4*>(Kh + go);
                *reinterpret_cast<uint4*>(smf + oKL + 2 * (r * 72 + c8)) =
                    *reinterpret_cast<const uint4*>(Kl + go);
            }
            const long vbase = (long)(b * 512 + h * 64) * 512 + kb * 128;
            for (int i = tid; i < 1024; i += 512) {
                const int r = i >> 4, c8 = (i & 15) * 8;
                const long go = vbase + (long)r * 512 + c8;
                *reinterpret_cast<uint4*>(smf + oVH + 2 * (r * 136 + c8)) =
                    *reinterpret_cast<const uint4*>(Vh + go);
                *reinterpret_cast<uint4*>(smf + oVL + 2 * (r * 136 + c8)) =
                    *reinterpret_cast<const uint4*>(Vl + go);
            }
        }
        __syncthreads();

        float acc_s[2][4][4];
        #pragma unroll
        for (int i = 0; i < 2; i++)
            #pragma unroll
            for (int j = 0; j < 4; j++)
                #pragma unroll
                for (int q = 0; q < 4; q++) acc_s[i][j][q] = 0.f;

        #pragma unroll
        for (int ks = 0; ks < 4; ks++) {
            const int acol = ks * 16 + (lane >> 4) * 8;
            uint32_t afh[2][4], afl[2][4];
            #pragma unroll
            for (int mt = 0; mt < 2; mt++) {
                const uint32_t ad = sb + oQH +
                    2u * (uint32_t)((wm * 32 + mt * 16 + (lane & 15)) * 72 + acol);
                ldm4(afh[mt], ad);
                ldm4(afl[mt], ad + (oQL - oQH));
            }
            uint32_t bfh[8], bfl[8];
            #pragma unroll
            for (int p = 0; p < 2; p++) {
                const int n = wn * 32 + (p * 2 + (bmat >> 1)) * 8 + bmr;
                const int koff = ks * 16 + (bmat & 1) * 8;
                const uint32_t bd = sb + oKH + 2u * (uint32_t)(n * 72 + koff);
                ldm4(&bfh[p * 4], bd);
                ldm4(&bfl[p * 4], bd + (oKL - oKH));
            }
            #pragma unroll
            for (int mt = 0; mt < 2; mt++) {
                #pragma unroll
                for (int n4 = 0; n4 < 4; n4++) {
                    const int bi = (n4 >> 1) * 4 + (n4 & 1) * 2;
                    mma16816(acc_s[mt][n4], afh[mt], bfh[bi], bfh[bi + 1]);
                    mma16816(acc_s[mt][n4], afh[mt], bfl[bi], bfl[bi + 1]);
                    mma16816(acc_s[mt][n4], afl[mt], bfh[bi], bfh[bi + 1]);
                }
            }
        }

        #pragma unroll
        for (int mt = 0; mt < 2; mt++) {
            #pragma unroll
            for (int half = 0; half < 2; half++) {
                float vmax = -1e30f;
                #pragma unroll
                for (int n4 = 0; n4 < 4; n4++)
                    vmax = fmaxf(vmax, fmaxf(acc_s[mt][n4][half * 2], acc_s[mt][n4][half * 2 + 1]));
                vmax = fmaxf(vmax, __shfl_xor_sync(0xffffffffu, vmax, 1));
                vmax = fmaxf(vmax, __shfl_xor_sync(0xffffffffu, vmax, 2));
                if ((lane & 3) == 0) {
                    const int row = wm * 32 + mt * 16 + half * 8 + (lane >> 2);
                    pm[row * 4 + wn] = vmax;
                }
            }
        }
        __syncthreads();
        if (tid < 128) {
            const float mb = fmaxf(fmaxf(pm[tid * 4], pm[tid * 4 + 1]),
                                   fmaxf(pm[tid * 4 + 2], pm[tid * 4 + 3]));
            const float mn = fmaxf(mrow[tid], mb);
            srow[tid] = __expf(mrow[tid] - mn);
            mrow[tid] = mn;
        }
        __syncthreads();

        #pragma unroll
        for (int mt = 0; mt < 2; mt++) {
            #pragma unroll
            for (int half = 0; half < 2; half++) {
                const int row = wm * 32 + mt * 16 + half * 8 + (lane >> 2);
                const float mi = mrow[row];
                float rs = 0.f;
                #pragma unroll
                for (int n4 = 0; n4 < 4; n4++) {
                    const float p0 = __expf(acc_s[mt][n4][half * 2 + 0] - mi);
                    const float p1 = __expf(acc_s[mt][n4][half * 2 + 1] - mi);
                    rs += p0 + p1;
                    const int col = wn * 32 + n4 * 8 + (lane & 3) * 2;
                    __nv_bfloat16 h0, h1, l0, l1;
                    split2(p0, h0, l0); split2(p1, h1, l1);
                    *reinterpret_cast<uint32_t*>(smf + oPH + 2 * (row * 136 + col)) = pack2(h0, h1);
                    *reinterpret_cast<uint32_t*>(smf + oPL + 2 * (row * 136 + col)) = pack2(l0, l1);
                }
                rs += __shfl_xor_sync(0xffffffffu, rs, 1);
                rs += __shfl_xor_sync(0xffffffffu, rs, 2);
                if ((lane & 3) == 0) ps[row * 4 + wn] = rs;
            }
        }
        __syncthreads();

        if (tid < 128)
            lrow[tid] = lrow[tid] * srow[tid] +
                        (ps[tid * 4] + ps[tid * 4 + 1] + ps[tid * 4 + 2] + ps[tid * 4 + 3]);

        {
            const int r0 = om * 16 + (lane >> 2);
            const float s0 = srow[r0], s1 = srow[r0 + 8];
            #pragma unroll
            for (int n4 = 0; n4 < 4; n4++) {
                acc_o[n4][0] *= s0; acc_o[n4][1] *= s0;
                acc_o[n4][2] *= s1; acc_o[n4][3] *= s1;
            }
        }

        #pragma unroll
        for (int ks2 = 0; ks2 < 8; ks2++) {
            const int acol = ks2 * 16 + (lane >> 4) * 8;
            uint32_t pah[4], pal[4];
            {
                const uint32_t ad = sb + oPH +
                    2u * (uint32_t)((om * 16 + (lane & 15)) * 136 + acol);
                ldm4(pah, ad);
                ldm4(pal, ad + (oPL - oPH));
            }
            uint32_t bfh[8], bfl[8];
            #pragma unroll
            for (int p = 0; p < 2; p++) {
                const int n = on * 32 + (p * 2 + (bmat >> 1)) * 8 + bmr;
                const int koff = ks2 * 16 + (bmat & 1) * 8;
                const uint32_t bd = sb + oVH + 2u * (uint32_t)(n * 136 + koff);
                ldm4(&bfh[p * 4], bd);
                ldm4(&bfl[p * 4], bd + (oVL - oVH));
            }
            #pragma unroll
            for (int n4 = 0; n4 < 4; n4++) {
                const int bi = (n4 >> 1) * 4 + (n4 & 1) * 2;
                mma16816(acc_o[n4], pah, bfh[bi], bfh[bi + 1]);
                mma16816(acc_o[n4], pah, bfl[bi], bfl[bi + 1]);
                mma16816(acc_o[n4], pal, bfh[bi], bfh[bi + 1]);
            }
        }
        __syncthreads();
    }

    if (tid < 128) srow[tid] = 1.f / lrow[tid];
    __syncthreads();
    {
        const int r0 = om * 16 + (lane >> 2);
        const float i0 = srow[r0], i1 = srow[r0 + 8];
        const long gq = (long)(b * 512 + qt * 128);
        #pragma unroll
        for (int n4 = 0; n4 < 4; n4++) {
            const int c0 = on * 32 + n4 * 8 + (lane & 3) * 2;
            const float v00 = acc_o[n4][0] * i0, v01 = acc_o[n4][1] * i0;
            const float v10 = acc_o[n4][2] * i1, v11 = acc_o[n4][3] * i1;
            const long a0 = (gq + r0) * 512 + h * 64 + c0;
            const long a1 = (gq + r0 + 8) * 512 + h * 64 + c0;
            __nv_bfloat16 h0, h1, l0, l1;
            split2(v00, h0, l0); split2(v01, h1, l1);
            *reinterpret_cast<uint32_t*>(Ch + a0) = pack2(h0, h1);
            *reinterpret_cast<uint32_t*>(Cl + a0) = pack2(l0, l1);
            split2(v10, h0, l0); split2(v11, h1, l1);
            *reinterpret_cast<uint32_t*>(Ch + a1) = pack2(h0, h1);
            *reinterpret_cast<uint32_t*>(Cl + a1) = pack2(l0, l1);
        }
    }
}

// ---------------- fp32 -> bf16 hi/lo split with zero-padding -------------------
__global__ void split_kernel(const float* __restrict__ src, __nv_bfloat16* __restrict__ hi,
                             __nv_bfloat16* __restrict__ lo, int rs, int cs, int rd, int cd)
{
    const long idx4 = ((long)blockIdx.x * blockDim.x + threadIdx.x) * 4;
    if (idx4 >= (long)rd * cd) return;
    const int r = (int)(idx4 / cd), c = (int)(idx4 % cd);
    float4 v = make_float4(0.f, 0.f, 0.f, 0.f);
    if (r < rs && c < cs) v = *reinterpret_cast<const float4*>(src + (long)r * cs + c);
    __nv_bfloat16 h0, h1, h2, h3, l0, l1, l2, l3;
    split2(v.x, h0, l0); split2(v.y, h1, l1); split2(v.z, h2, l2); split2(v.w, h3, l3);
    *reinterpret_cast<uint2*>(hi + idx4) = make_uint2(pack2(h0, h1), pack2(h2, h3));
    *reinterpret_cast<uint2*>(lo + idx4) = make_uint2(pack2(l0, l1), pack2(l2, l3));
}

__global__ void pad_bias2(const float* __restrict__ s1, float* __restrict__ d1,
                          const float* __restrict__ s2, float* __restrict__ d2, int n) {
    const int i = threadIdx.x;
    if (blockIdx.x == 0) d1[i] = (i < n) ? s1[i] : 0.f;
    else                 d2[i] = (i < n) ? s2[i] : 0.f;
}

// ---------------- 2-D LayerNorm over (S,D) per batch ---------------------------
template<bool PAIR>
__global__ __launch_bounds__(1024)
void layernorm_kernel(const float* __restrict__ X, const float* __restrict__ Add,
                      const float* __restrict__ gamma, const float* __restrict__ beta,
                      float* __restrict__ out, __nv_bfloat16* __restrict__ oh,
                      __nv_bfloat16* __restrict__ ol)
{
    const long base = (long)blockIdx.x * LN_N;
    float s1 = 0.f, s2 = 0.f;
    for (int i = threadIdx.x * 4; i < LN_N; i += 4096) {
        float4 v = *reinterpret_cast<const float4*>(X + base + i);
        if (Add) {
            float4 a = *reinterpret_cast<const float4*>(Add + base + i);
            v.x += a.x; v.y += a.y; v.z += a.z; v.w += a.w;
        }
        s1 += (v.x + v.y) + (v.z + v.w);
        s2 += (v.x*v.x + v.y*v.y) + (v.z*v.z + v.w*v.w);
    }
    __shared__ float r1[32], r2[32];
    const int lane = threadIdx.x & 31, wid = threadIdx.x >> 5;
    #pragma unroll
    for (int o = 16; o; o >>= 1) {
        s1 += __shfl_xor_sync(0xffffffffu, s1, o);
        s2 += __shfl_xor_sync(0xffffffffu, s2, o);
    }
    if (!lane) { r1[wid] = s1; r2[wid] = s2; }
    __syncthreads();
    if (threadIdx.x < 32) {
        s1 = r1[threadIdx.x]; s2 = r2[threadIdx.x];
        #pragma unroll
        for (int o = 16; o; o >>= 1) {
            s1 += __shfl_xor_sync(0xffffffffu, s1, o);
            s2 += __shfl_xor_sync(0xffffffffu, s2, o);
        }
        if (!threadIdx.x) { r1[0] = s1; r2[0] = s2; }
    }
    __syncthreads();
    const float mean = r1[0] / (float)LN_N;
    const float var  = r2[0] / (float)LN_N - mean * mean;
    const float rstd = rsqrtf(var + 1e-5f);

    for (int i = threadIdx.x * 4; i < LN_N; i += 4096) {
        float4 v = *reinterpret_cast<const float4*>(X + base + i);
        if (Add) {
            float4 a = *reinterpret_cast<const float4*>(Add + base + i);
            v.x += a.x; v.y += a.y; v.z += a.z; v.w += a.w;
        }
        float4 g  = *reinterpret_cast<const float4*>(gamma + i);
        float4 bt = *reinterpret_cast<const float4*>(beta  + i);
        float4 o;
        o.x = (v.x - mean) * rstd * g.x + bt.x;
        o.y = (v.y - mean) * rstd * g.y + bt.y;
        o.z = (v.z - mean) * rstd * g.z + bt.z;
        o.w = (v.w - mean) * rstd * g.w + bt.w;
        *reinterpret_cast<float4*>(out + base + i) = o;
        if (PAIR) {
            __nv_bfloat16 h0, h1, h2, h3, l0, l1, l2, l3;
            split2(o.x, h0, l0); split2(o.y, h1, l1); split2(o.z, h2, l2); split2(o.w, h3, l3);
            *reinterpret_cast<uint2*>(oh + base + i) = make_uint2(pack2(h0, h1), pack2(h2, h3));
            *reinterpret_cast<uint2*>(ol + base + i) = make_uint2(pack2(l0, l1), pack2(l2, l3));
        }
    }
}

// ---------------- launch --------------------------------------------------------
extern "C" void kernel_launch(void* const* d_in, const int* in_sizes, int n_in,
                              void* d_out, int out_size)
{
    const float* x  = (const float*)d_in[0];
    const float* Wq = (const float*)d_in[1];
    const float* bq = (const float*)d_in[2];
    const float* Wk = (const float*)d_in[3];
    const float* bk = (const float*)d_in[4];
    const float* Wv = (const float*)d_in[5];
    const float* bv = (const float*)d_in[6];
    const float* Wo = (const float*)d_in[7];
    const float* bo = (const float*)d_in[8];
    const float* W1 = (const float*)d_in[9];
    const float* b1 = (const float*)d_in[10];
    const float* W2 = (const float*)d_in[11];
    const float* b2 = (const float*)d_in[12];
    const float* W3 = (const float*)d_in[13];
    const float* b3 = (const float*)d_in[14];
    const float* gamma = (const float*)d_in[15];
    const float* beta  = (const float*)d_in[16];
    float* out = (float*)d_out;

    unsigned char* ar;
    cudaGetSymbolAddress((void**)&ar, g_arena);
    #define BF(o) reinterpret_cast<__nv_bfloat16*>(ar + (o))
    #define FP(o) reinterpret_cast<float*>(ar + (o))

    const int SMG  = 2 * (2 * 128 * 40 + 2 * 128 * 40) * 2;   // 81920
    const int SMFL = 183808;
    cudaFuncSetAttribute((const void*)gemm_mma<0, false>, cudaFuncAttributeMaxDynamicSharedMemorySize, SMG);
    cudaFuncSetAttribute((const void*)gemm_mma<1, false>, cudaFuncAttributeMaxDynamicSharedMemorySize, SMG);
    cudaFuncSetAttribute((const void*)gemm_mma<1, true >, cudaFuncAttributeMaxDynamicSharedMemorySize, SMG);
    cudaFuncSetAttribute((const void*)gemm_mma<2, false>, cudaFuncAttributeMaxDynamicSharedMemorySize, SMG);
    cudaFuncSetAttribute((const void*)flash_attn, cudaFuncAttributeMaxDynamicSharedMemorySize, SMFL);

    // ---- splits (fp32 -> bf16 hi/lo, with padding) ----
    auto g4 = [](long n) { return (unsigned)((n / 4 + 255) / 256); };
    split_kernel<<<g4((long)NM*ND),   256>>>(x,  BF(O_XH),  BF(O_XL),  NM, ND, NM, ND);
    split_kernel<<<g4((long)ND*ND),   256>>>(Wq, BF(O_WQH), BF(O_WQL), ND, ND, ND, ND);
    split_kernel<<<g4((long)ND*ND),   256>>>(Wk, BF(O_WKH), BF(O_WKL), ND, ND, ND, ND);
    split_kernel<<<g4((long)ND*ND),   256>>>(Wv, BF(O_WVH), BF(O_WVL), ND, ND, ND, ND);
    split_kernel<<<g4((long)ND*ND),   256>>>(Wo, BF(O_WOH), BF(O_WOL), ND, ND, ND, ND);
    split_kernel<<<g4((long)NFP*ND),  256>>>(W1, BF(O_W1H), BF(O_W1L), NFF, ND,  NFP, ND);
    split_kernel<<<g4((long)NFP*NFP), 256>>>(W2, BF(O_W2H), BF(O_W2L), NFF, NFF, NFP, NFP);
    split_kernel<<<g4((long)ND*NFP),  256>>>(W3, BF(O_W3H), BF(O_W3L), ND,  NFF, ND,  NFP);
    pad_bias2<<<2, 256>>>(b1, FP(O_B1P), b2, FP(O_B2P), NFF);

    // ---- 1) Q/K/V projections (q pre-scaled by 1/8; v written transposed) ----
    {
        dim3 grid(4, 128, 1);
        gemm_mma<1, false><<<grid, 128, SMG>>>(
            BF(O_XH), BF(O_XL), BF(O_WQH), BF(O_WQL), bq, nullptr,
            nullptr, BF(O_QH), BF(O_QL), ND, ND, ND, ND, 0.125f);
        gemm_mma<1, false><<<grid, 128, SMG>>>(
            BF(O_XH), BF(O_XL), BF(O_WKH), BF(O_WKL), bk, nullptr,
            nullptr, BF(O_KH), BF(O_KL), ND, ND, ND, ND, 1.f);
        gemm_mma<2, false><<<grid, 128, SMG>>>(
            BF(O_XH), BF(O_XL), BF(O_WVH), BF(O_WVL), bv, nullptr,
            nullptr, BF(O_VTH), BF(O_VTL), ND, ND, ND, ND, 1.f);
    }

    // ---- 2-4) fused flash attention -> concat pairs ----
    {
        dim3 grid(4, NB * NH);
        flash_attn<<<grid, 512, SMFL>>>(
            BF(O_QH), BF(O_QL), BF(O_KH), BF(O_KL),
            BF(O_VTH), BF(O_VTL), BF(O_CCH), BF(O_CCL));
    }

    // ---- 5) y = concat @ Wo^T + bo + x  (fp32) ----
    {
        dim3 grid(4, 128, 1);
        gemm_mma<0, false><<<grid, 128, SMG>>>(
            BF(O_CCH), BF(O_CCL), BF(O_WOH), BF(O_WOL), bo, x,
            FP(O_Y), nullptr, nullptr, ND, ND, ND, ND, 1.f);
    }

    // ---- 6) y = LN(y), also emit bf16 pair ----
    layernorm_kernel<true><<<NB, 1024>>>(FP(O_Y), nullptr, gamma, beta,
                                         FP(O_Y), BF(O_YH), BF(O_YL));

    // ---- 7) f1 = relu(y @ W1p^T + b1p) pair, N=256 ----
    {
        dim3 grid(2, 128, 1);
        gemm_mma<1, true><<<grid, 128, SMG>>>(
            BF(O_YH), BF(O_YL), BF(O_W1H), BF(O_W1L), FP(O_B1P), nullptr,
            nullptr, BF(O_F1H), BF(O_F1L), ND, ND, ND, NFP, 1.f);
    }
    // ---- 8) f2 = relu(f1 @ W2p^T + b2p) pair, K=N=256 ----
    {
        dim3 grid(2, 128, 1);
        gemm_mma<1, true><<<grid, 128, SMG>>>(
            BF(O_F1H), BF(O_F1L), BF(O_W2H), BF(O_W2L), FP(O_B2P), nullptr,
            nullptr, BF(O_F2H), BF(O_F2L), NFP, NFP, NFP, NFP, 1.f);
    }
    // ---- 9) f3 = f2 @ W3p^T + b3 + y  (fp32, residual folded) ----
    {
        dim3 grid(4, 128, 1);
        gemm_mma<0, false><<<grid, 128, SMG>>>(
            BF(O_F2H), BF(O_F2L), BF(O_W3H), BF(O_W3L), b3, FP(O_Y),
            FP(O_F3), nullptr, nullptr, NFP, NFP, NFP, ND, 1.f);
    }

    // ---- 10) y2 = LN(f3)  (f3 already includes +y) ----
    layernorm_kernel<false><<<NB, 1024>>>(FP(O_F3), nullptr, gamma, beta,
                                          FP(O_Y2), nullptr, nullptr);
    // ---- 11) out = LN(y2) ----
    layernorm_kernel<false><<<NB, 1024>>>(FP(O_Y2), nullptr, gamma, beta,
                                          out, nullptr, nullptr);
}